// round 3
// baseline (speedup 1.0000x reference)
#include <cuda_runtime.h>
#include <cuda_bf16.h>
#include <math.h>

// ---------------------------------------------------------------------------
// PCN_37391985279556: B=4096 graphs x M=64 points, K=3-NN PointNet-ish net.
//
// Pipeline (all BN layers are training-mode batch stats -> fold as affine):
//  k_graph1 : per-graph knn + U=x@W1[:59] (f32x2 GEMM) + per-edge
//             relu(U[j]+rel@W1[59:62]+b1), K-max per node -> g_Hmax,
//             per-block (sum,sumsq) partials for BN1 stats.
//  k_red1   : reduce BN1 stats -> a1,c1 (affine).
//  k_fold2  : W2' = a1 (x) W2, b2' = b2 + c1@W2   (BN1 folded into GEMM2).
//  k_graph2 : per-graph h2 = relu(Hmax@W2'+b2') (f32x2 GEMM); emit per-graph
//             feature sums (mean-pool numerator) + sumsq partials for BN2.
//  k_red2   : BN2 stats -> a2,c2.
//  k_foldc1 : fold BN2+meanpool(1/64) into Wc1 -> Wc1f,bc1f.
//  k_cls1   : C1 = relu(Gsum@Wc1f+bc1f)  [4096,256] + BN3 stat partials.
//  k_red3   : BN3 stats folded into Wc2 -> Wc2f, bias.
//  k_z      : z = relu(C1bn@Wc2f + bias) [4096].
//  k_final  : BN over z (1 feature, 4096 rows) + sigmoid -> out.
// ---------------------------------------------------------------------------

#define BG 4096
#define MP 64
#define KN 3
#define FXF 59
#define F1 128
#define F2 128
#define FC 256
#define NN (BG*MP)            // 262144 nodes
#define NE (NN*KN)            // 786432 edges
#define EPSB 1e-5f

// ---- device scratch (no cudaMalloc allowed) ----
__device__ float g_Hmax[(size_t)NN*F1];     // 134 MB
__device__ float g_part1[BG*2*F1];          // BN1 per-block partials
__device__ float g_ab1[2*F1];               // a1 | c1
__device__ float g_W2p[F1*F2];
__device__ float g_b2p[F2];
__device__ float g_Gsum[BG*F2];             // per-graph sums of h2
__device__ float g_Qprt[BG*F2];             // per-graph sumsq of h2
__device__ float g_ab2[2*F2];               // a2 | c2
__device__ float g_Wc1f[F2*FC];
__device__ float g_bc1f[FC];
__device__ float g_C1[(size_t)BG*FC];
__device__ float g_part3[256*2*FC];
__device__ float g_Wc2f[FC+1];              // [256] = folded bias
__device__ float g_z[BG];

// ---- packed f32x2 helpers (FFMA2: PTX-only on sm_103a) ----
__device__ __forceinline__ unsigned long long pk2(float lo, float hi) {
    unsigned long long r;
    asm("mov.b64 %0,{%1,%2};" : "=l"(r) : "f"(lo), "f"(hi));
    return r;
}
__device__ __forceinline__ void upk2(unsigned long long v, float& lo, float& hi) {
    asm("mov.b64 {%0,%1},%2;" : "=f"(lo), "=f"(hi) : "l"(v));
}
__device__ __forceinline__ void fma2(unsigned long long& d,
                                     unsigned long long a, unsigned long long b) {
    asm("fma.rn.f32x2 %0,%1,%2,%0;" : "+l"(d) : "l"(a), "l"(b));
}

// ---- k_graph1 shared layout (floats) ----
// xsp [59][66]   node-pair-packed x^T      @0      (3894)
// ws  [62][128]  W1                        @3904   (7936)
// us  [64][128]  U = x@W1[:59]             @11840  (8192)
// bs  [128]      b1                        @20032
// ps  [64*3]     pos                       @20160
// srS [256], srQ [256]                     @20352 / 20608
// nbr [192] int                            @20864
#define SM1_FLOATS 21056
#define SM1_BYTES  (SM1_FLOATS*4)

__global__ __launch_bounds__(256)
void k_graph1(const float* __restrict__ x, const float* __restrict__ pos,
              const float* __restrict__ W1, const float* __restrict__ b1) {
    extern __shared__ float sm[];
    float* xsp = sm;
    float* ws  = sm + 3904;
    float* us  = sm + 11840;
    float* bs  = sm + 20032;
    float* ps  = sm + 20160;
    float* srS = sm + 20352;
    float* srQ = sm + 20608;
    int*   nbr = (int*)(sm + 20864);

    const int tid = threadIdx.x;
    const int g   = blockIdx.x;

    // --- loads (x transposed+pair-packed for f32x2 GEMM) ---
    const float* xg = x + (size_t)g * MP * FXF;   // contiguous 3776 floats
    for (int l = tid; l < MP * FXF; l += 256) {
        int i = l / FXF;
        int c = l - i * FXF;
        xsp[c * 66 + i] = xg[l];
    }
    for (int l = tid; l < 62 * F1; l += 256) ws[l] = W1[l];
    if (tid < F1) bs[tid] = b1[tid];
    for (int l = tid; l < MP * 3; l += 256) ps[l] = pos[(size_t)g * MP * 3 + l];
    __syncthreads();

    // --- knn (warps 0-1), overlapped with GEMM1 on other warps ---
    if (tid < MP) {
        int i = tid;
        float pix = ps[i*3], piy = ps[i*3+1], piz = ps[i*3+2];
        float d0 = 1e30f, d1 = 1e30f, d2 = 1e30f;
        int   j0 = 0, j1 = 0, j2 = 0;
        for (int j = 0; j < MP; j++) {
            if (j == i) continue;
            float dx = ps[j*3]   - pix;
            float dy = ps[j*3+1] - piy;
            float dz = ps[j*3+2] - piz;
            float d = dx*dx + dy*dy + dz*dz;
            if (d < d0)      { d2=d1; j2=j1; d1=d0; j1=j0; d0=d; j0=j; }
            else if (d < d1) { d2=d1; j2=j1; d1=d; j1=j; }
            else if (d < d2) { d2=d; j2=j; }
        }
        nbr[i*3] = j0; nbr[i*3+1] = j1; nbr[i*3+2] = j2;
    }

    // --- GEMM1: U[64,128] = x[64,59] @ W1[0:59,:]  (f32x2, node-pair packed)
    {
        const int fg = tid & 63;  const int f0 = fg * 2;
        const int pbase = (tid >> 6) * 8;           // 8 node-pairs = 16 nodes
        unsigned long long a[8][2];
#pragma unroll
        for (int p = 0; p < 8; p++) { a[p][0] = 0ull; a[p][1] = 0ull; }
        for (int c = 0; c < FXF; c++) {
            float2 wv = *(const float2*)&ws[c * F1 + f0];
            unsigned long long wa = pk2(wv.x, wv.x);
            unsigned long long wb = pk2(wv.y, wv.y);
            const float* xr = &xsp[c * 66 + pbase * 2];
#pragma unroll
            for (int p = 0; p < 8; p++) {
                unsigned long long xv = *(const unsigned long long*)(xr + p * 2);
                fma2(a[p][0], xv, wa);
                fma2(a[p][1], xv, wb);
            }
        }
#pragma unroll
        for (int p = 0; p < 8; p++) {
            int n = (pbase + p) * 2;
            float e, o;
            upk2(a[p][0], e, o); us[n*F1 + f0]   = e; us[(n+1)*F1 + f0]   = o;
            upk2(a[p][1], e, o); us[n*F1 + f0+1] = e; us[(n+1)*F1 + f0+1] = o;
        }
    }
    __syncthreads();

    // --- edges: relu(U[j] + rel@W1[59:62] + b1), K-max + BN1 stat partials
    {
        const int f    = tid & 127;
        const int half = tid >> 7;
        const float w59 = ws[59*F1 + f];
        const float w60 = ws[60*F1 + f];
        const float w61 = ws[61*F1 + f];
        const float bf  = bs[f];
        float s = 0.f, q = 0.f;
        float* outg = g_Hmax + (size_t)g * MP * F1;
        for (int ii = 0; ii < 32; ii++) {
            int i = half * 32 + ii;
            float pix = ps[i*3], piy = ps[i*3+1], piz = ps[i*3+2];
            float hm = 0.f;   // relu values are >= 0
#pragma unroll
            for (int k = 0; k < KN; k++) {
                int j = nbr[i*3 + k];
                float r0 = ps[j*3]   - pix;
                float r1 = ps[j*3+1] - piy;
                float r2 = ps[j*3+2] - piz;
                float v = us[j*F1 + f] + bf + r0*w59 + r1*w60 + r2*w61;
                float r = fmaxf(v, 0.f);
                s += r; q += r * r;
                hm = fmaxf(hm, r);
            }
            outg[i * F1 + f] = hm;
        }
        srS[half * 128 + f] = s;
        srQ[half * 128 + f] = q;
    }
    __syncthreads();
    if (tid < F1) {
        g_part1[g*256 + tid]       = srS[tid] + srS[128 + tid];
        g_part1[g*256 + 128 + tid] = srQ[tid] + srQ[128 + tid];
    }
}

__global__ void k_red1(const float* __restrict__ g1, const float* __restrict__ be1) {
    __shared__ float sS[256], sQ[256];
    const int f = blockIdx.x, tid = threadIdx.x;
    float s = 0.f, q = 0.f;
    for (int i = tid; i < BG; i += 256) {
        s += g_part1[i*256 + f];
        q += g_part1[i*256 + 128 + f];
    }
    sS[tid] = s; sQ[tid] = q; __syncthreads();
    for (int st = 128; st > 0; st >>= 1) {
        if (tid < st) { sS[tid] += sS[tid+st]; sQ[tid] += sQ[tid+st]; }
        __syncthreads();
    }
    if (tid == 0) {
        float inv = 1.f / (float)NE;
        float mu  = sS[0] * inv;
        float var = sQ[0] * inv - mu * mu;
        float a   = g1[f] * rsqrtf(var + EPSB);
        g_ab1[f]       = a;
        g_ab1[128 + f] = be1[f] - mu * a;
    }
}

__global__ void k_fold2(const float* __restrict__ W2, const float* __restrict__ b2) {
    __shared__ float sa[128], sc[128];
    const int tid = threadIdx.x;            // 128 threads
    sa[tid] = g_ab1[tid];
    sc[tid] = g_ab1[128 + tid];
    __syncthreads();
    float bacc = b2[tid];
    for (int c = 0; c < 128; c++) {
        float w = W2[c*128 + tid];
        g_W2p[c*128 + tid] = sa[c] * w;
        bacc += sc[c] * w;
    }
    g_b2p[tid] = bacc;
}

// ---- k_graph2 shared layout (floats) ----
// hsp [128][66] @0 (8448), w2s @8448 (16384), b2s @24832 (128),
// rS @24960 (512), rQ @25472 (512)
#define SM2_FLOATS 25984
#define SM2_BYTES  (SM2_FLOATS*4)

__global__ __launch_bounds__(256)
void k_graph2() {
    extern __shared__ float sm[];
    float* hsp = sm;
    float* w2s = sm + 8448;
    float* b2s = sm + 24832;
    float* rS  = sm + 24960;
    float* rQ  = sm + 25472;

    const int tid = threadIdx.x;
    const int g   = blockIdx.x;

    const float* Hg = g_Hmax + (size_t)g * MP * F1;
    for (int l = tid; l < MP * F1; l += 256) {
        int n = l >> 7, c = l & 127;
        hsp[c * 66 + n] = Hg[l];
    }
    for (int l = tid; l < F1 * F2; l += 256) w2s[l] = g_W2p[l];
    if (tid < F2) b2s[tid] = g_b2p[tid];
    __syncthreads();

    const int fg = tid & 63;  const int f0 = fg * 2;
    const int ngp = tid >> 6; const int pbase = ngp * 8;
    unsigned long long a[8][2];
#pragma unroll
    for (int p = 0; p < 8; p++) { a[p][0] = 0ull; a[p][1] = 0ull; }
    for (int c = 0; c < F1; c++) {
        float2 wv = *(const float2*)&w2s[c * F2 + f0];
        unsigned long long wa = pk2(wv.x, wv.x);
        unsigned long long wb = pk2(wv.y, wv.y);
        const float* xr = &hsp[c * 66 + pbase * 2];
#pragma unroll
        for (int p = 0; p < 8; p++) {
            unsigned long long xv = *(const unsigned long long*)(xr + p * 2);
            fma2(a[p][0], xv, wa);
            fma2(a[p][1], xv, wb);
        }
    }
    const float b0 = b2s[f0], b1v = b2s[f0 + 1];
    float s0 = 0.f, q0 = 0.f, s1 = 0.f, q1 = 0.f;
#pragma unroll
    for (int p = 0; p < 8; p++) {
        float e, o, v;
        upk2(a[p][0], e, o);
        v = fmaxf(e + b0, 0.f);  s0 += v; q0 += v*v;
        v = fmaxf(o + b0, 0.f);  s0 += v; q0 += v*v;
        upk2(a[p][1], e, o);
        v = fmaxf(e + b1v, 0.f); s1 += v; q1 += v*v;
        v = fmaxf(o + b1v, 0.f); s1 += v; q1 += v*v;
    }
    rS[ngp*128 + f0]   = s0;  rS[ngp*128 + f0+1] = s1;
    rQ[ngp*128 + f0]   = q0;  rQ[ngp*128 + f0+1] = q1;
    __syncthreads();
    if (tid < F2) {
        float S = rS[tid] + rS[128+tid] + rS[256+tid] + rS[384+tid];
        float Q = rQ[tid] + rQ[128+tid] + rQ[256+tid] + rQ[384+tid];
        g_Gsum[g*F2 + tid] = S;
        g_Qprt[g*F2 + tid] = Q;
    }
}

__global__ void k_red2(const float* __restrict__ g2, const float* __restrict__ be2) {
    __shared__ float sS[256], sQ[256];
    const int f = blockIdx.x, tid = threadIdx.x;
    float s = 0.f, q = 0.f;
    for (int i = tid; i < BG; i += 256) {
        s += g_Gsum[i*F2 + f];
        q += g_Qprt[i*F2 + f];
    }
    sS[tid] = s; sQ[tid] = q; __syncthreads();
    for (int st = 128; st > 0; st >>= 1) {
        if (tid < st) { sS[tid] += sS[tid+st]; sQ[tid] += sQ[tid+st]; }
        __syncthreads();
    }
    if (tid == 0) {
        float inv = 1.f / (float)NN;
        float mu  = sS[0] * inv;
        float var = sQ[0] * inv - mu * mu;
        float a   = g2[f] * rsqrtf(var + EPSB);
        g_ab2[f]       = a;
        g_ab2[128 + f] = be2[f] - mu * a;
    }
}

__global__ void k_foldc1(const float* __restrict__ Wc1, const float* __restrict__ bc1) {
    __shared__ float sa[128], sc[128];
    const int tid = threadIdx.x;            // 256 threads
    if (tid < 128) {
        sa[tid] = g_ab2[tid] * (1.f / 64.f);   // fold mean-pool /M
        sc[tid] = g_ab2[128 + tid];
    }
    __syncthreads();
    float bacc = bc1[tid];
    for (int c = 0; c < 128; c++) {
        float w = Wc1[c*256 + tid];
        g_Wc1f[c*256 + tid] = sa[c] * w;
        bacc += sc[c] * w;
    }
    g_bc1f[tid] = bacc;
}

__global__ __launch_bounds__(256)
void k_cls1() {
    __shared__ float gs[16 * 128];
    const int tid = threadIdx.x;
    const int blk = blockIdx.x;             // 16 rows per block
    const float* G = g_Gsum + (size_t)blk * 16 * F2;
    for (int l = tid; l < 16 * 128; l += 256) gs[l] = G[l];
    __syncthreads();
    float acc[16];
    const float bb = g_bc1f[tid];
#pragma unroll
    for (int r = 0; r < 16; r++) acc[r] = bb;
    for (int c = 0; c < 128; c++) {
        float w = g_Wc1f[c*256 + tid];
#pragma unroll
        for (int r = 0; r < 16; r++) acc[r] += gs[r*128 + c] * w;
    }
    float s = 0.f, q = 0.f;
#pragma unroll
    for (int r = 0; r < 16; r++) {
        float v = fmaxf(acc[r], 0.f);
        g_C1[((size_t)blk * 16 + r) * 256 + tid] = v;
        s += v; q += v * v;
    }
    g_part3[blk*512 + tid]       = s;
    g_part3[blk*512 + 256 + tid] = q;
}

__global__ void k_red3(const float* __restrict__ gc1, const float* __restrict__ bec1,
                       const float* __restrict__ Wc2, const float* __restrict__ bc2) {
    __shared__ float red[256];
    const int tid = threadIdx.x;            // 256 threads, one per feature
    float s = 0.f, q = 0.f;
    for (int i = 0; i < 256; i++) {
        s += g_part3[i*512 + tid];
        q += g_part3[i*512 + 256 + tid];
    }
    float inv = 1.f / (float)BG;
    float mu  = s * inv;
    float var = q * inv - mu * mu;
    float a   = gc1[tid] * rsqrtf(var + EPSB);
    float c   = bec1[tid] - mu * a;
    float w   = Wc2[tid];                   // Wc2 shape [256,1]
    g_Wc2f[tid] = a * w;
    red[tid] = c * w;
    __syncthreads();
    for (int st = 128; st > 0; st >>= 1) {
        if (tid < st) red[tid] += red[tid + st];
        __syncthreads();
    }
    if (tid == 0) g_Wc2f[256] = bc2[0] + red[0];
}

__global__ void k_z() {
    const int tid  = threadIdx.x;
    const int w    = tid >> 5;
    const int lane = tid & 31;
    const int r    = blockIdx.x * 8 + w;    // 512 blocks x 8 warps = 4096 rows
    const float* row = g_C1 + (size_t)r * 256;
    float acc = 0.f;
#pragma unroll
    for (int t = 0; t < 8; t++) {
        int idx = lane + t * 32;
        acc += row[idx] * g_Wc2f[idx];
    }
    for (int off = 16; off; off >>= 1)
        acc += __shfl_down_sync(0xffffffffu, acc, off);
    if (lane == 0) g_z[r] = fmaxf(acc + g_Wc2f[256], 0.f);
}

__global__ void k_final(const float* __restrict__ gc2, const float* __restrict__ bec2,
                        float* __restrict__ out) {
    __shared__ float sS[512], sQ[512];
    const int tid = threadIdx.x;            // 512 threads x 8
    float s = 0.f, q = 0.f;
    float zv[8];
#pragma unroll
    for (int t = 0; t < 8; t++) {
        float v = g_z[tid + 512 * t];
        zv[t] = v; s += v; q += v * v;
    }
    sS[tid] = s; sQ[tid] = q; __syncthreads();
    for (int st = 256; st > 0; st >>= 1) {
        if (tid < st) { sS[tid] += sS[tid+st]; sQ[tid] += sQ[tid+st]; }
        __syncthreads();
    }
    float inv = 1.f / (float)BG;
    float mu  = sS[0] * inv;
    float var = sQ[0] * inv - mu * mu;
    float a   = gc2[0] * rsqrtf(var + EPSB);
    float b   = bec2[0];
#pragma unroll
    for (int t = 0; t < 8; t++) {
        float tt = a * (zv[t] - mu) + b;
        out[tid + 512 * t] = 1.f / (1.f + expf(-tt));
    }
}

extern "C" void kernel_launch(void* const* d_in, const int* in_sizes, int n_in,
                              void* d_out, int out_size) {
    const float* x    = (const float*)d_in[0];
    const float* pos  = (const float*)d_in[1];
    // d_in[2] = batch (layout known: repeat(arange(B),M)) -> unused
    const float* W1   = (const float*)d_in[3];
    const float* b1   = (const float*)d_in[4];
    const float* g1   = (const float*)d_in[5];
    const float* be1  = (const float*)d_in[6];
    const float* W2   = (const float*)d_in[7];
    const float* b2   = (const float*)d_in[8];
    const float* g2   = (const float*)d_in[9];
    const float* be2  = (const float*)d_in[10];
    const float* Wc1  = (const float*)d_in[11];
    const float* bc1  = (const float*)d_in[12];
    const float* gc1  = (const float*)d_in[13];
    const float* bec1 = (const float*)d_in[14];
    const float* Wc2  = (const float*)d_in[15];
    const float* bc2  = (const float*)d_in[16];
    const float* gc2  = (const float*)d_in[17];
    const float* bec2 = (const float*)d_in[18];

    // Idempotent, non-stream API: safe under graph capture.
    cudaFuncSetAttribute(k_graph1, cudaFuncAttributeMaxDynamicSharedMemorySize, SM1_BYTES);
    cudaFuncSetAttribute(k_graph2, cudaFuncAttributeMaxDynamicSharedMemorySize, SM2_BYTES);

    k_graph1<<<BG, 256, SM1_BYTES>>>(x, pos, W1, b1);
    k_red1  <<<128, 256>>>(g1, be1);
    k_fold2 <<<1, 128>>>(W2, b2);
    k_graph2<<<BG, 256, SM2_BYTES>>>();
    k_red2  <<<128, 256>>>(g2, be2);
    k_foldc1<<<1, 256>>>(Wc1, bc1);
    k_cls1  <<<256, 256>>>();
    k_red3  <<<1, 256>>>(gc1, bec1, Wc2, bc2);
    k_z     <<<512, 256>>>();
    k_final <<<1, 512>>>(gc2, bec2, (float*)d_out);
}

// round 8
// speedup vs baseline: 1.1388x; 1.1388x over previous
#include <cuda_runtime.h>
#include <cuda_bf16.h>
#include <math.h>

// ---------------------------------------------------------------------------
// PCN_37391985279556: B=4096 graphs x M=64 points, K=3-NN PointNet-ish net.
// All-FFMA2 implementation (tcgen05 unavailable: harness targets compute_103
// family PTX, ptxas rejects arch-specific tcgen05).
//
//  k_graph1   : per-graph knn (4-way parallel) + U=x@W1[:59] (f32x2 GEMM)
//               + edge relu/K-max -> g_Hmax + BN1 stat partials.
//  k_red1     : BN1 stats -> affine (a1,c1).
//  k_fold2    : fold BN1 into W2 -> g_W2p, b2'.
//  k_graph2_p : persistent ONE-GEMM [262144,128]@[128,128] f32x2, weights
//               resident in smem, A-tiles register-prefetched (LDG overlaps
//               GEMM), fused bias+relu + per-graph sum/sumsq epilogue.
//  k_red2 ... k_final : classifier tail (BN folds).
// ---------------------------------------------------------------------------

#define BG 4096
#define MP 64
#define KN 3
#define FXF 59
#define F1 128
#define F2 128
#define FC 256
#define NN (BG*MP)            // 262144 nodes
#define NE (NN*KN)            // 786432 edges
#define EPSB 1e-5f

// ---- device scratch ----
__device__ float g_Hmax[(size_t)NN*F1];     // 134 MB
__device__ float g_part1[BG*2*F1];
__device__ float g_ab1[2*F1];
__device__ float g_W2p[F1*F2];
__device__ float g_b2p[F2];
__device__ float g_Gsum[BG*F2];
__device__ float g_Qprt[BG*F2];
__device__ float g_ab2[2*F2];
__device__ float g_Wc1f[F2*FC];
__device__ float g_bc1f[FC];
__device__ float g_C1[(size_t)BG*FC];
__device__ float g_part3[256*2*FC];
__device__ float g_Wc2f[FC+1];
__device__ float g_z[BG];

// ---- packed f32x2 helpers ----
__device__ __forceinline__ unsigned long long pk2(float lo, float hi) {
    unsigned long long r;
    asm("mov.b64 %0,{%1,%2};" : "=l"(r) : "f"(lo), "f"(hi));
    return r;
}
__device__ __forceinline__ void upk2(unsigned long long v, float& lo, float& hi) {
    asm("mov.b64 {%0,%1},%2;" : "=f"(lo), "=f"(hi) : "l"(v));
}
__device__ __forceinline__ void fma2(unsigned long long& d,
                                     unsigned long long a, unsigned long long b) {
    asm("fma.rn.f32x2 %0,%1,%2,%0;" : "+l"(d) : "l"(a), "l"(b));
}

// ========================= k_graph1 =========================================
// smem floats: XS[59][68]@0, WS[62][128]@4012, US[64][128]@11948, BS@20140,
// PS@20268(192), KD@20460(768), KJ@21228(768,int), SRS@21996, SRQ@22252,
// NBR@22508(192,int)  -> total 22700 floats
#define XS_O 0
#define WS_O 4012
#define US_O 11948
#define BS_O 20140
#define PS_O 20268
#define KD_O 20460
#define KJ_O 21228
#define SRS_O 21996
#define SRQ_O 22252
#define NBR_O 22508
#define SM1_FLOATS 22700
#define SM1_BYTES (SM1_FLOATS*4)

__global__ __launch_bounds__(256, 2)
void k_graph1(const float* __restrict__ x, const float* __restrict__ pos,
              const float* __restrict__ W1, const float* __restrict__ b1) {
    extern __shared__ float sm[];
    float* xsp = sm + XS_O;
    float* ws  = sm + WS_O;
    float* us  = sm + US_O;
    float* bs  = sm + BS_O;
    float* ps  = sm + PS_O;
    float* kd  = sm + KD_O;
    int*   kj  = (int*)(sm + KJ_O);
    float* srS = sm + SRS_O;
    float* srQ = sm + SRQ_O;
    int*   nbr = (int*)(sm + NBR_O);

    const int tid = threadIdx.x;
    const int g   = blockIdx.x;

    // --- loads ---
    const float* xg = x + (size_t)g * MP * FXF;
    for (int l = tid; l < MP * FXF; l += 256) {
        int i = l / FXF;
        int c = l - i * FXF;
        xsp[c * 68 + i] = xg[l];
    }
    for (int l = tid; l < 62 * F1; l += 256) ws[l] = W1[l];
    if (tid < F1) bs[tid] = b1[tid];
    for (int l = tid; l < MP * 3; l += 256) ps[l] = pos[(size_t)g * MP * 3 + l];
    __syncthreads();

    // --- knn partials: 4 threads per point, 16 candidates each ---
    {
        const int i   = tid & 63;
        const int blk = tid >> 6;
        float pix = ps[i*3], piy = ps[i*3+1], piz = ps[i*3+2];
        float d0 = 1e30f, d1 = 1e30f, d2 = 1e30f;
        int   j0 = 0, j1 = 0, j2 = 0;
#pragma unroll
        for (int jj = 0; jj < 16; jj++) {
            int j = blk * 16 + jj;
            float dx = ps[j*3]   - pix;
            float dy = ps[j*3+1] - piy;
            float dz = ps[j*3+2] - piz;
            float d = dx*dx + dy*dy + dz*dz;
            if (j == i) d = 1e30f;
            if (d < d0)      { d2=d1; j2=j1; d1=d0; j1=j0; d0=d; j0=j; }
            else if (d < d1) { d2=d1; j2=j1; d1=d; j1=j; }
            else if (d < d2) { d2=d; j2=j; }
        }
        kd[tid*3] = d0; kd[tid*3+1] = d1; kd[tid*3+2] = d2;
        kj[tid*3] = j0; kj[tid*3+1] = j1; kj[tid*3+2] = j2;
    }
    __syncthreads();

    // --- knn merge (tid<64), concurrent with GEMM on other warps ---
    if (tid < 64) {
        float d0 = 1e30f, d1 = 1e30f, d2 = 1e30f;
        int   j0 = 0, j1 = 0, j2 = 0;
#pragma unroll
        for (int b = 0; b < 4; b++) {
#pragma unroll
            for (int t = 0; t < 3; t++) {
                float d = kd[(b*64 + tid)*3 + t];
                int   j = kj[(b*64 + tid)*3 + t];
                if (d < d0)      { d2=d1; j2=j1; d1=d0; j1=j0; d0=d; j0=j; }
                else if (d < d1) { d2=d1; j2=j1; d1=d; j1=j; }
                else if (d < d2) { d2=d; j2=j; }
            }
        }
        nbr[tid*3] = j0; nbr[tid*3+1] = j1; nbr[tid*3+2] = j2;
    }

    // --- GEMM1: U[64,128] = x[64,59] @ W1[0:59,:]   4 cols x 4 pairs ---
    {
        const int f0 = (tid & 31) * 4;
        const int pb = (tid >> 5) * 4;          // pair base (4 pairs = 8 nodes)
        unsigned long long a[4][4];
#pragma unroll
        for (int p = 0; p < 4; p++)
#pragma unroll
            for (int c = 0; c < 4; c++) a[p][c] = 0ull;
#pragma unroll 4
        for (int c = 0; c < FXF; c++) {
            float4 w4 = *(const float4*)&ws[c * F1 + f0];
            unsigned long long w0 = pk2(w4.x, w4.x);
            unsigned long long w1 = pk2(w4.y, w4.y);
            unsigned long long w2 = pk2(w4.z, w4.z);
            unsigned long long w3 = pk2(w4.w, w4.w);
            const float* xr = &xsp[c * 68 + pb * 2];
            ulonglong2 xA = *(const ulonglong2*)(xr);
            ulonglong2 xB = *(const ulonglong2*)(xr + 4);
            fma2(a[0][0], xA.x, w0); fma2(a[0][1], xA.x, w1);
            fma2(a[0][2], xA.x, w2); fma2(a[0][3], xA.x, w3);
            fma2(a[1][0], xA.y, w0); fma2(a[1][1], xA.y, w1);
            fma2(a[1][2], xA.y, w2); fma2(a[1][3], xA.y, w3);
            fma2(a[2][0], xB.x, w0); fma2(a[2][1], xB.x, w1);
            fma2(a[2][2], xB.x, w2); fma2(a[2][3], xB.x, w3);
            fma2(a[3][0], xB.y, w0); fma2(a[3][1], xB.y, w1);
            fma2(a[3][2], xB.y, w2); fma2(a[3][3], xB.y, w3);
        }
#pragma unroll
        for (int p = 0; p < 4; p++) {
            int n = (pb + p) * 2;
            float e0,o0,e1,o1,e2,o2,e3,o3;
            upk2(a[p][0], e0, o0); upk2(a[p][1], e1, o1);
            upk2(a[p][2], e2, o2); upk2(a[p][3], e3, o3);
            *(float4*)&us[n*F1 + f0]     = make_float4(e0, e1, e2, e3);
            *(float4*)&us[(n+1)*F1 + f0] = make_float4(o0, o1, o2, o3);
        }
    }
    __syncthreads();

    // --- edges: relu(U[j] + rel@W1[59:62] + b1), K-max + BN1 partials ---
    {
        const int f    = tid & 127;
        const int half = tid >> 7;
        const float w59 = ws[59*F1 + f];
        const float w60 = ws[60*F1 + f];
        const float w61 = ws[61*F1 + f];
        const float bf  = bs[f];
        float s = 0.f, q = 0.f;
        float* outg = g_Hmax + (size_t)g * MP * F1;
        for (int ii = 0; ii < 32; ii++) {
            int i = half * 32 + ii;
            float pix = ps[i*3], piy = ps[i*3+1], piz = ps[i*3+2];
            float hm = 0.f;
#pragma unroll
            for (int k = 0; k < KN; k++) {
                int j = nbr[i*3 + k];
                float r0 = ps[j*3]   - pix;
                float r1 = ps[j*3+1] - piy;
                float r2 = ps[j*3+2] - piz;
                float v = us[j*F1 + f] + bf + r0*w59 + r1*w60 + r2*w61;
                float r = fmaxf(v, 0.f);
                s += r; q += r * r;
                hm = fmaxf(hm, r);
            }
            outg[i * F1 + f] = hm;
        }
        srS[half * 128 + f] = s;
        srQ[half * 128 + f] = q;
    }
    __syncthreads();
    if (tid < F1) {
        g_part1[g*256 + tid]       = srS[tid] + srS[128 + tid];
        g_part1[g*256 + 128 + tid] = srQ[tid] + srQ[128 + tid];
    }
}

__global__ void k_red1(const float* __restrict__ g1, const float* __restrict__ be1) {
    __shared__ float sS[256], sQ[256];
    const int f = blockIdx.x, tid = threadIdx.x;
    float s = 0.f, q = 0.f;
    for (int i = tid; i < BG; i += 256) {
        s += g_part1[i*256 + f];
        q += g_part1[i*256 + 128 + f];
    }
    sS[tid] = s; sQ[tid] = q; __syncthreads();
    for (int st = 128; st > 0; st >>= 1) {
        if (tid < st) { sS[tid] += sS[tid+st]; sQ[tid] += sQ[tid+st]; }
        __syncthreads();
    }
    if (tid == 0) {
        float inv = 1.f / (float)NE;
        float mu  = sS[0] * inv;
        float var = sQ[0] * inv - mu * mu;
        float a   = g1[f] * rsqrtf(var + EPSB);
        g_ab1[f]       = a;
        g_ab1[128 + f] = be1[f] - mu * a;
    }
}

__global__ void k_fold2(const float* __restrict__ W2, const float* __restrict__ b2) {
    __shared__ float sa[128], sc[128];
    const int tid = threadIdx.x;            // 128 threads
    sa[tid] = g_ab1[tid];
    sc[tid] = g_ab1[128 + tid];
    __syncthreads();
    float bacc = b2[tid];
    for (int c = 0; c < 128; c++) {
        float w = W2[c*128 + tid];
        g_W2p[c*128 + tid] = sa[c] * w;
        bacc += sc[c] * w;
    }
    g_b2p[tid] = bacc;
}

// ========================= k_graph2_p (persistent FFMA2 GEMM) ===============
// smem floats: WS2[128][128]@0, HT[128][132]@16384,
// SS[8][128]@33280, SQ[8][128]@34304  -> 35328 floats = 141312 B
#define WS2_O 0
#define HT_O  16384
#define HT_STRIDE 132
#define SS_O 33280
#define SQ_O 34304
#define SM2_FLOATS 35328
#define SM2_BYTES (SM2_FLOATS*4)
#define NT2 2048
#define GRID2 148

__global__ __launch_bounds__(256, 1)
void k_graph2_p() {
    extern __shared__ float sm[];
    float* ws2  = sm + WS2_O;
    float* hT   = sm + HT_O;
    float* sS   = sm + SS_O;
    float* sQ   = sm + SQ_O;

    const int tid = threadIdx.x;
    const int wid = tid >> 5;

    // one-time weight residency
    for (int i = tid; i < 4096; i += 256)
        *(float4*)&ws2[i*4] = *(const float4*)&g_W2p[i*4];

    const int f0 = (tid & 31) * 4;
    const int pb = (tid >> 5) * 8;          // 8 pairs = 16 nodes per warp-row
    const float bb0 = g_b2p[f0], bb1 = g_b2p[f0+1],
                bb2 = g_b2p[f0+2], bb3 = g_b2p[f0+3];

    const int nd = (tid + 0 * 256) >> 5;    // this thread's node strip params
    // prefetch registers: 16 float4 = one 64KB tile's worth across 256 threads
    float4 pre[16];
    int tile = blockIdx.x;
    {
        const float* src = g_Hmax + (size_t)tile * 128 * 128;
#pragma unroll
        for (int u = 0; u < 16; u++) {
            int c = tid + u * 256;
            pre[u] = *(const float4*)(src + (c >> 5) * 128 + (c & 31) * 4);
        }
    }
    (void)nd;

    for (; tile < NT2; tile += GRID2) {
        __syncthreads();                    // hT free (prev epilogue done)
        // commit prefetched A tile -> transposed hT[k][node]
#pragma unroll
        for (int u = 0; u < 16; u++) {
            int c  = tid + u * 256;
            int n  = c >> 5;
            int q  = c & 31;
            float4 v = pre[u];
            hT[(q*4    ) * HT_STRIDE + n] = v.x;
            hT[(q*4 + 1) * HT_STRIDE + n] = v.y;
            hT[(q*4 + 2) * HT_STRIDE + n] = v.z;
            hT[(q*4 + 3) * HT_STRIDE + n] = v.w;
        }
        __syncthreads();

        // issue next tile's LDGs now; they complete during the GEMM below
        int ntile = tile + GRID2;
        if (ntile < NT2) {
            const float* src = g_Hmax + (size_t)ntile * 128 * 128;
#pragma unroll
            for (int u = 0; u < 16; u++) {
                int c = tid + u * 256;
                pre[u] = *(const float4*)(src + (c >> 5) * 128 + (c & 31) * 4);
            }
        }

        // GEMM: 4 cols x 8 pairs per thread
        unsigned long long a[8][4];
#pragma unroll
        for (int p = 0; p < 8; p++)
#pragma unroll
            for (int c = 0; c < 4; c++) a[p][c] = 0ull;
#pragma unroll 4
        for (int c = 0; c < F1; c++) {
            float4 w4 = *(const float4*)&ws2[c * F2 + f0];
            unsigned long long w0 = pk2(w4.x, w4.x);
            unsigned long long w1 = pk2(w4.y, w4.y);
            unsigned long long w2 = pk2(w4.z, w4.z);
            unsigned long long w3 = pk2(w4.w, w4.w);
            const float* xr = &hT[c * HT_STRIDE + pb * 2];
            ulonglong2 xA = *(const ulonglong2*)(xr);
            ulonglong2 xB = *(const ulonglong2*)(xr + 4);
            ulonglong2 xC = *(const ulonglong2*)(xr + 8);
            ulonglong2 xD = *(const ulonglong2*)(xr + 12);
            fma2(a[0][0], xA.x, w0); fma2(a[0][1], xA.x, w1);
            fma2(a[0][2], xA.x, w2); fma2(a[0][3], xA.x, w3);
            fma2(a[1][0], xA.y, w0); fma2(a[1][1], xA.y, w1);
            fma2(a[1][2], xA.y, w2); fma2(a[1][3], xA.y, w3);
            fma2(a[2][0], xB.x, w0); fma2(a[2][1], xB.x, w1);
            fma2(a[2][2], xB.x, w2); fma2(a[2][3], xB.x, w3);
            fma2(a[3][0], xB.y, w0); fma2(a[3][1], xB.y, w1);
            fma2(a[3][2], xB.y, w2); fma2(a[3][3], xB.y, w3);
            fma2(a[4][0], xC.x, w0); fma2(a[4][1], xC.x, w1);
            fma2(a[4][2], xC.x, w2); fma2(a[4][3], xC.x, w3);
            fma2(a[5][0], xC.y, w0); fma2(a[5][1], xC.y, w1);
            fma2(a[5][2], xC.y, w2); fma2(a[5][3], xC.y, w3);
            fma2(a[6][0], xD.x, w0); fma2(a[6][1], xD.x, w1);
            fma2(a[6][2], xD.x, w2); fma2(a[6][3], xD.x, w3);
            fma2(a[7][0], xD.y, w0); fma2(a[7][1], xD.y, w1);
            fma2(a[7][2], xD.y, w2); fma2(a[7][3], xD.y, w3);
        }

        // epilogue: bias + relu, per-thread column sums over its 16 nodes
        float sv0=0.f,sv1=0.f,sv2=0.f,sv3=0.f;
        float qv0=0.f,qv1=0.f,qv2=0.f,qv3=0.f;
#pragma unroll
        for (int p = 0; p < 8; p++) {
            float e, o, v;
            upk2(a[p][0], e, o);
            v = fmaxf(e + bb0, 0.f); sv0 += v; qv0 += v*v;
            v = fmaxf(o + bb0, 0.f); sv0 += v; qv0 += v*v;
            upk2(a[p][1], e, o);
            v = fmaxf(e + bb1, 0.f); sv1 += v; qv1 += v*v;
            v = fmaxf(o + bb1, 0.f); sv1 += v; qv1 += v*v;
            upk2(a[p][2], e, o);
            v = fmaxf(e + bb2, 0.f); sv2 += v; qv2 += v*v;
            v = fmaxf(o + bb2, 0.f); sv2 += v; qv2 += v*v;
            upk2(a[p][3], e, o);
            v = fmaxf(e + bb3, 0.f); sv3 += v; qv3 += v*v;
            v = fmaxf(o + bb3, 0.f); sv3 += v; qv3 += v*v;
        }
        sS[wid*128 + f0] = sv0; sS[wid*128 + f0+1] = sv1;
        sS[wid*128 + f0+2] = sv2; sS[wid*128 + f0+3] = sv3;
        sQ[wid*128 + f0] = qv0; sQ[wid*128 + f0+1] = qv1;
        sQ[wid*128 + f0+2] = qv2; sQ[wid*128 + f0+3] = qv3;
        __syncthreads();
        {
            int col  = tid & 127;
            int gsel = tid >> 7;            // warps 0-3: nodes 0-63 (graph even)
            int r0 = gsel * 4;
            float S = sS[(r0  )*128+col] + sS[(r0+1)*128+col]
                    + sS[(r0+2)*128+col] + sS[(r0+3)*128+col];
            float Q = sQ[(r0  )*128+col] + sQ[(r0+1)*128+col]
                    + sQ[(r0+2)*128+col] + sQ[(r0+3)*128+col];
            int g = tile * 2 + gsel;
            g_Gsum[g*128 + col] = S;
            g_Qprt[g*128 + col] = Q;
        }
    }
}

// ========================= classifier tail ==================================
__global__ void k_red2(const float* __restrict__ g2, const float* __restrict__ be2) {
    __shared__ float sS[256], sQ[256];
    const int f = blockIdx.x, tid = threadIdx.x;
    float s = 0.f, q = 0.f;
    for (int i = tid; i < BG; i += 256) {
        s += g_Gsum[i*F2 + f];
        q += g_Qprt[i*F2 + f];
    }
    sS[tid] = s; sQ[tid] = q; __syncthreads();
    for (int st = 128; st > 0; st >>= 1) {
        if (tid < st) { sS[tid] += sS[tid+st]; sQ[tid] += sQ[tid+st]; }
        __syncthreads();
    }
    if (tid == 0) {
        float inv = 1.f / (float)NN;
        float mu  = sS[0] * inv;
        float var = sQ[0] * inv - mu * mu;
        float a   = g2[f] * rsqrtf(var + EPSB);
        g_ab2[f]       = a;
        g_ab2[128 + f] = be2[f] - mu * a;
    }
}

__global__ void k_foldc1(const float* __restrict__ Wc1, const float* __restrict__ bc1) {
    __shared__ float sa[128], sc[128];
    const int tid = threadIdx.x;            // 256 threads
    if (tid < 128) {
        sa[tid] = g_ab2[tid] * (1.f / 64.f);
        sc[tid] = g_ab2[128 + tid];
    }
    __syncthreads();
    float bacc = bc1[tid];
    for (int c = 0; c < 128; c++) {
        float w = Wc1[c*256 + tid];
        g_Wc1f[c*256 + tid] = sa[c] * w;
        bacc += sc[c] * w;
    }
    g_bc1f[tid] = bacc;
}

__global__ __launch_bounds__(256)
void k_cls1() {
    __shared__ float gs[16 * 128];
    const int tid = threadIdx.x;
    const int blk = blockIdx.x;
    const float* G = g_Gsum + (size_t)blk * 16 * F2;
    for (int l = tid; l < 16 * 128; l += 256) gs[l] = G[l];
    __syncthreads();
    float acc[16];
    const float bb = g_bc1f[tid];
#pragma unroll
    for (int r = 0; r < 16; r++) acc[r] = bb;
    for (int c = 0; c < 128; c++) {
        float w = g_Wc1f[c*256 + tid];
#pragma unroll
        for (int r = 0; r < 16; r++) acc[r] += gs[r*128 + c] * w;
    }
    float s = 0.f, q = 0.f;
#pragma unroll
    for (int r = 0; r < 16; r++) {
        float v = fmaxf(acc[r], 0.f);
        g_C1[((size_t)blk * 16 + r) * 256 + tid] = v;
        s += v; q += v * v;
    }
    g_part3[blk*512 + tid]       = s;
    g_part3[blk*512 + 256 + tid] = q;
}

__global__ void k_red3(const float* __restrict__ gc1, const float* __restrict__ bec1,
                       const float* __restrict__ Wc2, const float* __restrict__ bc2) {
    __shared__ float red[256];
    const int tid = threadIdx.x;
    float s = 0.f, q = 0.f;
    for (int i = 0; i < 256; i++) {
        s += g_part3[i*512 + tid];
        q += g_part3[i*512 + 256 + tid];
    }
    float inv = 1.f / (float)BG;
    float mu  = s * inv;
    float var = q * inv - mu * mu;
    float a   = gc1[tid] * rsqrtf(var + EPSB);
    float c   = bec1[tid] - mu * a;
    float w   = Wc2[tid];
    g_Wc2f[tid] = a * w;
    red[tid] = c * w;
    __syncthreads();
    for (int st = 128; st > 0; st >>= 1) {
        if (tid < st) red[tid] += red[tid + st];
        __syncthreads();
    }
    if (tid == 0) g_Wc2f[256] = bc2[0] + red[0];
}

__global__ void k_z() {
    const int tid  = threadIdx.x;
    const int w    = tid >> 5;
    const int lane = tid & 31;
    const int r    = blockIdx.x * 8 + w;
    const float* row = g_C1 + (size_t)r * 256;
    float acc = 0.f;
#pragma unroll
    for (int t = 0; t < 8; t++) {
        int idx = lane + t * 32;
        acc += row[idx] * g_Wc2f[idx];
    }
    for (int off = 16; off; off >>= 1)
        acc += __shfl_down_sync(0xffffffffu, acc, off);
    if (lane == 0) g_z[r] = fmaxf(acc + g_Wc2f[256], 0.f);
}

__global__ void k_final(const float* __restrict__ gc2, const float* __restrict__ bec2,
                        float* __restrict__ out) {
    __shared__ float sS[512], sQ[512];
    const int tid = threadIdx.x;
    float s = 0.f, q = 0.f;
    float zv[8];
#pragma unroll
    for (int t = 0; t < 8; t++) {
        float v = g_z[tid + 512 * t];
        zv[t] = v; s += v; q += v * v;
    }
    sS[tid] = s; sQ[tid] = q; __syncthreads();
    for (int st = 256; st > 0; st >>= 1) {
        if (tid < st) { sS[tid] += sS[tid+st]; sQ[tid] += sQ[tid+st]; }
        __syncthreads();
    }
    float inv = 1.f / (float)BG;
    float mu  = sS[0] * inv;
    float var = sQ[0] * inv - mu * mu;
    float a   = gc2[0] * rsqrtf(var + EPSB);
    float b   = bec2[0];
#pragma unroll
    for (int t = 0; t < 8; t++) {
        float tt = a * (zv[t] - mu) + b;
        out[tid + 512 * t] = 1.f / (1.f + expf(-tt));
    }
}

extern "C" void kernel_launch(void* const* d_in, const int* in_sizes, int n_in,
                              void* d_out, int out_size) {
    const float* x    = (const float*)d_in[0];
    const float* pos  = (const float*)d_in[1];
    const float* W1   = (const float*)d_in[3];
    const float* b1   = (const float*)d_in[4];
    const float* g1   = (const float*)d_in[5];
    const float* be1  = (const float*)d_in[6];
    const float* W2   = (const float*)d_in[7];
    const float* b2   = (const float*)d_in[8];
    const float* g2   = (const float*)d_in[9];
    const float* be2  = (const float*)d_in[10];
    const float* Wc1  = (const float*)d_in[11];
    const float* bc1  = (const float*)d_in[12];
    const float* gc1  = (const float*)d_in[13];
    const float* bec1 = (const float*)d_in[14];
    const float* Wc2  = (const float*)d_in[15];
    const float* bc2  = (const float*)d_in[16];
    const float* gc2  = (const float*)d_in[17];
    const float* bec2 = (const float*)d_in[18];

    cudaFuncSetAttribute(k_graph1,   cudaFuncAttributeMaxDynamicSharedMemorySize, SM1_BYTES);
    cudaFuncSetAttribute(k_graph2_p, cudaFuncAttributeMaxDynamicSharedMemorySize, SM2_BYTES);

    k_graph1  <<<BG, 256, SM1_BYTES>>>(x, pos, W1, b1);
    k_red1    <<<128, 256>>>(g1, be1);
    k_fold2   <<<1, 128>>>(W2, b2);
    k_graph2_p<<<GRID2, 256, SM2_BYTES>>>();
    k_red2    <<<128, 256>>>(g2, be2);
    k_foldc1  <<<1, 256>>>(Wc1, bc1);
    k_cls1    <<<256, 256>>>();
    k_red3    <<<1, 256>>>(gc1, bec1, Wc2, bc2);
    k_z       <<<512, 256>>>();
    k_final   <<<1, 512>>>(gc2, bec2, (float*)d_out);
}

// round 9
// speedup vs baseline: 1.1771x; 1.0336x over previous
#include <cuda_runtime.h>
#include <cuda_bf16.h>
#include <math.h>

// ---------------------------------------------------------------------------
// PCN_37391985279556: B=4096 graphs x M=64 points, K=3-NN PointNet-ish net.
// All-FFMA2 implementation (tcgen05 unavailable in this harness).
//
//  k_graph1   : per-graph knn + U=x@W1[:59]+b1 (f32x2 GEMM) + f32x2 edge
//               relu/K-max -> g_Hmax + BN1 stat partials.
//  k_red1     : BN1 stats -> affine (a1,c1).
//  k_fold2    : fold BN1 into W2 -> g_W2p, b2'.
//  k_graph2_p : persistent ONE-GEMM [262144,128]@[128,128] f32x2 @512thr,
//               weights resident, A-tiles register-prefetched, fused
//               bias+relu + per-graph sum/sumsq epilogue.
//  k_red2 ... k_final : classifier tail (BN folds).
// ---------------------------------------------------------------------------

#define BG 4096
#define MP 64
#define KN 3
#define FXF 59
#define F1 128
#define F2 128
#define FC 256
#define NN (BG*MP)            // 262144 nodes
#define NE (NN*KN)            // 786432 edges
#define EPSB 1e-5f

// ---- device scratch ----
__device__ float g_Hmax[(size_t)NN*F1];     // 134 MB
__device__ float g_part1[BG*2*F1];
__device__ float g_ab1[2*F1];
__device__ float g_W2p[F1*F2];
__device__ float g_b2p[F2];
__device__ float g_Gsum[BG*F2];
__device__ float g_Qprt[BG*F2];
__device__ float g_ab2[2*F2];
__device__ float g_Wc1f[F2*FC];
__device__ float g_bc1f[FC];
__device__ float g_C1[(size_t)BG*FC];
__device__ float g_part3[256*2*FC];
__device__ float g_Wc2f[FC+1];
__device__ float g_z[BG];

// ---- packed f32x2 helpers ----
__device__ __forceinline__ unsigned long long pk2(float lo, float hi) {
    unsigned long long r;
    asm("mov.b64 %0,{%1,%2};" : "=l"(r) : "f"(lo), "f"(hi));
    return r;
}
__device__ __forceinline__ void upk2(unsigned long long v, float& lo, float& hi) {
    asm("mov.b64 {%0,%1},%2;" : "=f"(lo), "=f"(hi) : "l"(v));
}
__device__ __forceinline__ void fma2(unsigned long long& d,
                                     unsigned long long a, unsigned long long b) {
    asm("fma.rn.f32x2 %0,%1,%2,%0;" : "+l"(d) : "l"(a), "l"(b));
}

// ========================= k_graph1 =========================================
// smem floats:
// XS[59][68]@0 (4012), WS[62][128]@4012 (7936), US[64][128]@11948 (8192),
// BS@20140 (128), PS@20268 (192), KD@20460 (768), KJ@21228 (768,int),
// RELP@21996 (1152: 192 edges x 3 x float2-dup), SRS@23148 (512),
// SRQ@23660 (512), NBR@24172 (192,int) -> 24364 floats = 97456 B
#define XS_O 0
#define WS_O 4012
#define US_O 11948
#define BS_O 20140
#define PS_O 20268
#define KD_O 20460
#define KJ_O 21228
#define RELP_O 21996
#define SRS_O 23148
#define SRQ_O 23660
#define NBR_O 24172
#define SM1_FLOATS 24364
#define SM1_BYTES (SM1_FLOATS*4)

__global__ __launch_bounds__(256, 2)
void k_graph1(const float* __restrict__ x, const float* __restrict__ pos,
              const float* __restrict__ W1, const float* __restrict__ b1) {
    extern __shared__ float sm[];
    float* xsp  = sm + XS_O;
    float* ws   = sm + WS_O;
    float* us   = sm + US_O;
    float* bs   = sm + BS_O;
    float* ps   = sm + PS_O;
    float* kd   = sm + KD_O;
    int*   kj   = (int*)(sm + KJ_O);
    float* relp = sm + RELP_O;
    float* srS  = sm + SRS_O;
    float* srQ  = sm + SRQ_O;
    int*   nbr  = (int*)(sm + NBR_O);

    const int tid = threadIdx.x;
    const int g   = blockIdx.x;

    // --- loads ---
    const float* xg = x + (size_t)g * MP * FXF;
    for (int l = tid; l < MP * FXF; l += 256) {
        int i = l / FXF;
        int c = l - i * FXF;
        xsp[c * 68 + i] = xg[l];
    }
    for (int l = tid; l < 62 * F1; l += 256) ws[l] = W1[l];
    if (tid < F1) bs[tid] = b1[tid];
    for (int l = tid; l < MP * 3; l += 256) ps[l] = pos[(size_t)g * MP * 3 + l];
    __syncthreads();

    // --- knn partials: 4 threads per point, 16 candidates each ---
    {
        const int i   = tid & 63;
        const int blk = tid >> 6;
        float pix = ps[i*3], piy = ps[i*3+1], piz = ps[i*3+2];
        float d0 = 1e30f, d1 = 1e30f, d2 = 1e30f;
        int   j0 = 0, j1 = 0, j2 = 0;
#pragma unroll
        for (int jj = 0; jj < 16; jj++) {
            int j = blk * 16 + jj;
            float dx = ps[j*3]   - pix;
            float dy = ps[j*3+1] - piy;
            float dz = ps[j*3+2] - piz;
            float d = dx*dx + dy*dy + dz*dz;
            if (j == i) d = 1e30f;
            if (d < d0)      { d2=d1; j2=j1; d1=d0; j1=j0; d0=d; j0=j; }
            else if (d < d1) { d2=d1; j2=j1; d1=d; j1=j; }
            else if (d < d2) { d2=d; j2=j; }
        }
        kd[tid*3] = d0; kd[tid*3+1] = d1; kd[tid*3+2] = d2;
        kj[tid*3] = j0; kj[tid*3+1] = j1; kj[tid*3+2] = j2;
    }
    __syncthreads();

    // --- knn merge (tid<64), concurrent with GEMM on other warps ---
    if (tid < 64) {
        float d0 = 1e30f, d1 = 1e30f, d2 = 1e30f;
        int   j0 = 0, j1 = 0, j2 = 0;
#pragma unroll
        for (int b = 0; b < 4; b++) {
#pragma unroll
            for (int t = 0; t < 3; t++) {
                float d = kd[(b*64 + tid)*3 + t];
                int   j = kj[(b*64 + tid)*3 + t];
                if (d < d0)      { d2=d1; j2=j1; d1=d0; j1=j0; d0=d; j0=j; }
                else if (d < d1) { d2=d1; j2=j1; d1=d; j1=j; }
                else if (d < d2) { d2=d; j2=j; }
            }
        }
        nbr[tid*3] = j0; nbr[tid*3+1] = j1; nbr[tid*3+2] = j2;
    }

    // --- GEMM1: U[64,128] = x[64,59] @ W1[0:59,:] + b1  (4 cols x 4 pairs)
    {
        const int f0 = (tid & 31) * 4;
        const int pb = (tid >> 5) * 4;          // pair base (4 pairs = 8 nodes)
        unsigned long long a[4][4];
#pragma unroll
        for (int p = 0; p < 4; p++)
#pragma unroll
            for (int c = 0; c < 4; c++) a[p][c] = 0ull;
#pragma unroll 4
        for (int c = 0; c < FXF; c++) {
            float4 w4 = *(const float4*)&ws[c * F1 + f0];
            unsigned long long w0 = pk2(w4.x, w4.x);
            unsigned long long w1 = pk2(w4.y, w4.y);
            unsigned long long w2 = pk2(w4.z, w4.z);
            unsigned long long w3 = pk2(w4.w, w4.w);
            const float* xr = &xsp[c * 68 + pb * 2];
            ulonglong2 xA = *(const ulonglong2*)(xr);
            ulonglong2 xB = *(const ulonglong2*)(xr + 4);
            fma2(a[0][0], xA.x, w0); fma2(a[0][1], xA.x, w1);
            fma2(a[0][2], xA.x, w2); fma2(a[0][3], xA.x, w3);
            fma2(a[1][0], xA.y, w0); fma2(a[1][1], xA.y, w1);
            fma2(a[1][2], xA.y, w2); fma2(a[1][3], xA.y, w3);
            fma2(a[2][0], xB.x, w0); fma2(a[2][1], xB.x, w1);
            fma2(a[2][2], xB.x, w2); fma2(a[2][3], xB.x, w3);
            fma2(a[3][0], xB.y, w0); fma2(a[3][1], xB.y, w1);
            fma2(a[3][2], xB.y, w2); fma2(a[3][3], xB.y, w3);
        }
        // fold bias here so the edge phase never touches it
        float4 b4 = *(const float4*)&bs[f0];
#pragma unroll
        for (int p = 0; p < 4; p++) {
            int n = (pb + p) * 2;
            float e0,o0,e1,o1,e2,o2,e3,o3;
            upk2(a[p][0], e0, o0); upk2(a[p][1], e1, o1);
            upk2(a[p][2], e2, o2); upk2(a[p][3], e3, o3);
            *(float4*)&us[n*F1 + f0] =
                make_float4(e0+b4.x, e1+b4.y, e2+b4.z, e3+b4.w);
            *(float4*)&us[(n+1)*F1 + f0] =
                make_float4(o0+b4.x, o1+b4.y, o2+b4.z, o3+b4.w);
        }
    }
    __syncthreads();

    // --- build duplicated rel pairs: relp[e][d] = float2(r,r), e=i*3+k ---
    if (tid < 192) {
        int i = tid / 3, k = tid - i * 3;
        int j = nbr[i*3 + k];
        float r0 = ps[j*3]   - ps[i*3];
        float r1 = ps[j*3+1] - ps[i*3+1];
        float r2 = ps[j*3+2] - ps[i*3+2];
        float2* rp = (float2*)relp + tid * 3;
        rp[0] = make_float2(r0, r0);
        rp[1] = make_float2(r1, r1);
        rp[2] = make_float2(r2, r2);
    }
    __syncthreads();

    // --- edges (f32x2): relu(U[j] + rel@W1[59:62]), K-max + BN1 partials ---
    {
        const int fp = tid & 63;        // feature pair
        const int f  = fp * 2;
        const int qt = tid >> 6;        // quarter: 16 points each
        unsigned long long w59p = *(const unsigned long long*)&ws[0];  // init
        unsigned long long w60p, w61p;
        w59p = *(const unsigned long long*)&ws[59*F1 + f];
        w60p = *(const unsigned long long*)&ws[60*F1 + f];
        w61p = *(const unsigned long long*)&ws[61*F1 + f];
        float s0 = 0.f, q0 = 0.f, s1 = 0.f, q1 = 0.f;
        float* outg = g_Hmax + (size_t)g * MP * F1;
        for (int ii = 0; ii < 16; ii++) {
            int i = qt * 16 + ii;
            float hm0 = 0.f, hm1 = 0.f;
#pragma unroll
            for (int k = 0; k < KN; k++) {
                int e = i * 3 + k;
                int j = nbr[e];
                const unsigned long long* rp =
                    (const unsigned long long*)relp + (size_t)e * 3;
                unsigned long long v2 = *(const unsigned long long*)&us[j*F1 + f];
                fma2(v2, rp[0], w59p);
                fma2(v2, rp[1], w60p);
                fma2(v2, rp[2], w61p);
                float ev, ov;
                upk2(v2, ev, ov);
                ev = fmaxf(ev, 0.f); ov = fmaxf(ov, 0.f);
                s0 += ev; q0 = fmaf(ev, ev, q0);
                s1 += ov; q1 = fmaf(ov, ov, q1);
                hm0 = fmaxf(hm0, ev); hm1 = fmaxf(hm1, ov);
            }
            *(float2*)&outg[i * F1 + f] = make_float2(hm0, hm1);
        }
        srS[qt * 128 + f] = s0; srS[qt * 128 + f + 1] = s1;
        srQ[qt * 128 + f] = q0; srQ[qt * 128 + f + 1] = q1;
    }
    __syncthreads();
    if (tid < F1) {
        float S = srS[tid] + srS[128+tid] + srS[256+tid] + srS[384+tid];
        float Q = srQ[tid] + srQ[128+tid] + srQ[256+tid] + srQ[384+tid];
        g_part1[g*256 + tid]       = S;
        g_part1[g*256 + 128 + tid] = Q;
    }
}

__global__ void k_red1(const float* __restrict__ g1, const float* __restrict__ be1) {
    __shared__ float sS[256], sQ[256];
    const int f = blockIdx.x, tid = threadIdx.x;
    float s = 0.f, q = 0.f;
    for (int i = tid; i < BG; i += 256) {
        s += g_part1[i*256 + f];
        q += g_part1[i*256 + 128 + f];
    }
    sS[tid] = s; sQ[tid] = q; __syncthreads();
    for (int st = 128; st > 0; st >>= 1) {
        if (tid < st) { sS[tid] += sS[tid+st]; sQ[tid] += sQ[tid+st]; }
        __syncthreads();
    }
    if (tid == 0) {
        float inv = 1.f / (float)NE;
        float mu  = sS[0] * inv;
        float var = sQ[0] * inv - mu * mu;
        float a   = g1[f] * rsqrtf(var + EPSB);
        g_ab1[f]       = a;
        g_ab1[128 + f] = be1[f] - mu * a;
    }
}

__global__ void k_fold2(const float* __restrict__ W2, const float* __restrict__ b2) {
    __shared__ float sa[128], sc[128];
    const int tid = threadIdx.x;            // 128 threads
    sa[tid] = g_ab1[tid];
    sc[tid] = g_ab1[128 + tid];
    __syncthreads();
    float bacc = b2[tid];
    for (int c = 0; c < 128; c++) {
        float w = W2[c*128 + tid];
        g_W2p[c*128 + tid] = sa[c] * w;
        bacc += sc[c] * w;
    }
    g_b2p[tid] = bacc;
}

// ========================= k_graph2_p (persistent FFMA2 GEMM, 512 thr) ======
// smem floats: WS2[128][128]@0, HT[128][132]@16384,
// SS[16][128]@33280, SQ[16][128]@35328  -> 37376 floats = 149504 B
#define WS2_O 0
#define HT_O  16384
#define HT_STRIDE 132
#define SS_O 33280
#define SQ_O 35328
#define SM2_FLOATS 37376
#define SM2_BYTES (SM2_FLOATS*4)
#define NT2 2048
#define GRID2 148

__global__ __launch_bounds__(512, 1)
void k_graph2_p() {
    extern __shared__ float sm[];
    float* ws2  = sm + WS2_O;
    float* hT   = sm + HT_O;
    float* sS   = sm + SS_O;
    float* sQ   = sm + SQ_O;

    const int tid = threadIdx.x;
    const int wid = tid >> 5;

    // one-time weight residency
    for (int i = tid; i < 4096; i += 512)
        *(float4*)&ws2[i*4] = *(const float4*)&g_W2p[i*4];

    const int f0 = (tid & 31) * 4;
    const int pb = wid * 4;                 // 4 pairs = 8 nodes per warp
    const float bb0 = g_b2p[f0], bb1 = g_b2p[f0+1],
                bb2 = g_b2p[f0+2], bb3 = g_b2p[f0+3];

    // prefetch registers: 8 float4 per thread = one 64KB tile across 512 thr
    float4 pre[8];
    int tile = blockIdx.x;
    {
        const float* src = g_Hmax + (size_t)tile * 128 * 128;
#pragma unroll
        for (int u = 0; u < 8; u++) {
            int c = tid + u * 512;
            pre[u] = *(const float4*)(src + (c >> 5) * 128 + (c & 31) * 4);
        }
    }

    for (; tile < NT2; tile += GRID2) {
        __syncthreads();                    // hT free (prev epilogue done)
        // commit prefetched A tile -> transposed hT[k][node]
#pragma unroll
        for (int u = 0; u < 8; u++) {
            int c  = tid + u * 512;
            int n  = c >> 5;
            int q  = c & 31;
            float4 v = pre[u];
            hT[(q*4    ) * HT_STRIDE + n] = v.x;
            hT[(q*4 + 1) * HT_STRIDE + n] = v.y;
            hT[(q*4 + 2) * HT_STRIDE + n] = v.z;
            hT[(q*4 + 3) * HT_STRIDE + n] = v.w;
        }
        __syncthreads();

        // issue next tile's LDGs now; they complete during the GEMM below
        int ntile = tile + GRID2;
        if (ntile < NT2) {
            const float* src = g_Hmax + (size_t)ntile * 128 * 128;
#pragma unroll
            for (int u = 0; u < 8; u++) {
                int c = tid + u * 512;
                pre[u] = *(const float4*)(src + (c >> 5) * 128 + (c & 31) * 4);
            }
        }

        // GEMM: 4 cols x 4 pairs (8 nodes) per thread
        unsigned long long a[4][4];
#pragma unroll
        for (int p = 0; p < 4; p++)
#pragma unroll
            for (int c = 0; c < 4; c++) a[p][c] = 0ull;
#pragma unroll 4
        for (int c = 0; c < F1; c++) {
            float4 w4 = *(const float4*)&ws2[c * F2 + f0];
            unsigned long long w0 = pk2(w4.x, w4.x);
            unsigned long long w1 = pk2(w4.y, w4.y);
            unsigned long long w2 = pk2(w4.z, w4.z);
            unsigned long long w3 = pk2(w4.w, w4.w);
            const float* xr = &hT[c * HT_STRIDE + pb * 2];
            ulonglong2 xA = *(const ulonglong2*)(xr);
            ulonglong2 xB = *(const ulonglong2*)(xr + 4);
            fma2(a[0][0], xA.x, w0); fma2(a[0][1], xA.x, w1);
            fma2(a[0][2], xA.x, w2); fma2(a[0][3], xA.x, w3);
            fma2(a[1][0], xA.y, w0); fma2(a[1][1], xA.y, w1);
            fma2(a[1][2], xA.y, w2); fma2(a[1][3], xA.y, w3);
            fma2(a[2][0], xB.x, w0); fma2(a[2][1], xB.x, w1);
            fma2(a[2][2], xB.x, w2); fma2(a[2][3], xB.x, w3);
            fma2(a[3][0], xB.y, w0); fma2(a[3][1], xB.y, w1);
            fma2(a[3][2], xB.y, w2); fma2(a[3][3], xB.y, w3);
        }

        // epilogue: bias + relu, per-thread column sums over its 8 nodes
        float sv0=0.f,sv1=0.f,sv2=0.f,sv3=0.f;
        float qv0=0.f,qv1=0.f,qv2=0.f,qv3=0.f;
#pragma unroll
        for (int p = 0; p < 4; p++) {
            float e, o, v;
            upk2(a[p][0], e, o);
            v = fmaxf(e + bb0, 0.f); sv0 += v; qv0 += v*v;
            v = fmaxf(o + bb0, 0.f); sv0 += v; qv0 += v*v;
            upk2(a[p][1], e, o);
            v = fmaxf(e + bb1, 0.f); sv1 += v; qv1 += v*v;
            v = fmaxf(o + bb1, 0.f); sv1 += v; qv1 += v*v;
            upk2(a[p][2], e, o);
            v = fmaxf(e + bb2, 0.f); sv2 += v; qv2 += v*v;
            v = fmaxf(o + bb2, 0.f); sv2 += v; qv2 += v*v;
            upk2(a[p][3], e, o);
            v = fmaxf(e + bb3, 0.f); sv3 += v; qv3 += v*v;
            v = fmaxf(o + bb3, 0.f); sv3 += v; qv3 += v*v;
        }
        sS[wid*128 + f0] = sv0; sS[wid*128 + f0+1] = sv1;
        sS[wid*128 + f0+2] = sv2; sS[wid*128 + f0+3] = sv3;
        sQ[wid*128 + f0] = qv0; sQ[wid*128 + f0+1] = qv1;
        sQ[wid*128 + f0+2] = qv2; sQ[wid*128 + f0+3] = qv3;
        __syncthreads();
        if (tid < 256) {
            int col  = tid & 127;
            int gsel = tid >> 7;            // warps 0-7: nodes 0-63 (graph even)
            int r0 = gsel * 8;
            float S = 0.f, Q = 0.f;
#pragma unroll
            for (int w = 0; w < 8; w++) {
                S += sS[(r0 + w)*128 + col];
                Q += sQ[(r0 + w)*128 + col];
            }
            int g = tile * 2 + gsel;
            g_Gsum[g*128 + col] = S;
            g_Qprt[g*128 + col] = Q;
        }
    }
}

// ========================= classifier tail ==================================
__global__ void k_red2(const float* __restrict__ g2, const float* __restrict__ be2) {
    __shared__ float sS[256], sQ[256];
    const int f = blockIdx.x, tid = threadIdx.x;
    float s = 0.f, q = 0.f;
    for (int i = tid; i < BG; i += 256) {
        s += g_Gsum[i*F2 + f];
        q += g_Qprt[i*F2 + f];
    }
    sS[tid] = s; sQ[tid] = q; __syncthreads();
    for (int st = 128; st > 0; st >>= 1) {
        if (tid < st) { sS[tid] += sS[tid+st]; sQ[tid] += sQ[tid+st]; }
        __syncthreads();
    }
    if (tid == 0) {
        float inv = 1.f / (float)NN;
        float mu  = sS[0] * inv;
        float var = sQ[0] * inv - mu * mu;
        float a   = g2[f] * rsqrtf(var + EPSB);
        g_ab2[f]       = a;
        g_ab2[128 + f] = be2[f] - mu * a;
    }
}

__global__ void k_foldc1(const float* __restrict__ Wc1, const float* __restrict__ bc1) {
    __shared__ float sa[128], sc[128];
    const int tid = threadIdx.x;            // 256 threads
    if (tid < 128) {
        sa[tid] = g_ab2[tid] * (1.f / 64.f);
        sc[tid] = g_ab2[128 + tid];
    }
    __syncthreads();
    float bacc = bc1[tid];
    for (int c = 0; c < 128; c++) {
        float w = Wc1[c*256 + tid];
        g_Wc1f[c*256 + tid] = sa[c] * w;
        bacc += sc[c] * w;
    }
    g_bc1f[tid] = bacc;
}

__global__ __launch_bounds__(256)
void k_cls1() {
    __shared__ float gs[16 * 128];
    const int tid = threadIdx.x;
    const int blk = blockIdx.x;
    const float* G = g_Gsum + (size_t)blk * 16 * F2;
    for (int l = tid; l < 16 * 128; l += 256) gs[l] = G[l];
    __syncthreads();
    float acc[16];
    const float bb = g_bc1f[tid];
#pragma unroll
    for (int r = 0; r < 16; r++) acc[r] = bb;
    for (int c = 0; c < 128; c++) {
        float w = g_Wc1f[c*256 + tid];
#pragma unroll
        for (int r = 0; r < 16; r++) acc[r] += gs[r*128 + c] * w;
    }
    float s = 0.f, q = 0.f;
#pragma unroll
    for (int r = 0; r < 16; r++) {
        float v = fmaxf(acc[r], 0.f);
        g_C1[((size_t)blk * 16 + r) * 256 + tid] = v;
        s += v; q += v * v;
    }
    g_part3[blk*512 + tid]       = s;
    g_part3[blk*512 + 256 + tid] = q;
}

__global__ void k_red3(const float* __restrict__ gc1, const float* __restrict__ bec1,
                       const float* __restrict__ Wc2, const float* __restrict__ bc2) {
    __shared__ float red[256];
    const int tid = threadIdx.x;
    float s = 0.f, q = 0.f;
    for (int i = 0; i < 256; i++) {
        s += g_part3[i*512 + tid];
        q += g_part3[i*512 + 256 + tid];
    }
    float inv = 1.f / (float)BG;
    float mu  = s * inv;
    float var = q * inv - mu * mu;
    float a   = gc1[tid] * rsqrtf(var + EPSB);
    float c   = bec1[tid] - mu * a;
    float w   = Wc2[tid];
    g_Wc2f[tid] = a * w;
    red[tid] = c * w;
    __syncthreads();
    for (int st = 128; st > 0; st >>= 1) {
        if (tid < st) red[tid] += red[tid + st];
        __syncthreads();
    }
    if (tid == 0) g_Wc2f[256] = bc2[0] + red[0];
}

__global__ void k_z() {
    const int tid  = threadIdx.x;
    const int w    = tid >> 5;
    const int lane = tid & 31;
    const int r    = blockIdx.x * 8 + w;
    const float* row = g_C1 + (size_t)r * 256;
    float acc = 0.f;
#pragma unroll
    for (int t = 0; t < 8; t++) {
        int idx = lane + t * 32;
        acc += row[idx] * g_Wc2f[idx];
    }
    for (int off = 16; off; off >>= 1)
        acc += __shfl_down_sync(0xffffffffu, acc, off);
    if (lane == 0) g_z[r] = fmaxf(acc + g_Wc2f[256], 0.f);
}

__global__ void k_final(const float* __restrict__ gc2, const float* __restrict__ bec2,
                        float* __restrict__ out) {
    __shared__ float sS[512], sQ[512];
    const int tid = threadIdx.x;
    float s = 0.f, q = 0.f;
    float zv[8];
#pragma unroll
    for (int t = 0; t < 8; t++) {
        float v = g_z[tid + 512 * t];
        zv[t] = v; s += v; q += v * v;
    }
    sS[tid] = s; sQ[tid] = q; __syncthreads();
    for (int st = 256; st > 0; st >>= 1) {
        if (tid < st) { sS[tid] += sS[tid+st]; sQ[tid] += sQ[tid+st]; }
        __syncthreads();
    }
    float inv = 1.f / (float)BG;
    float mu  = sS[0] * inv;
    float var = sQ[0] * inv - mu * mu;
    float a   = gc2[0] * rsqrtf(var + EPSB);
    float b   = bec2[0];
#pragma unroll
    for (int t = 0; t < 8; t++) {
        float tt = a * (zv[t] - mu) + b;
        out[tid + 512 * t] = 1.f / (1.f + expf(-tt));
    }
}

extern "C" void kernel_launch(void* const* d_in, const int* in_sizes, int n_in,
                              void* d_out, int out_size) {
    const float* x    = (const float*)d_in[0];
    const float* pos  = (const float*)d_in[1];
    const float* W1   = (const float*)d_in[3];
    const float* b1   = (const float*)d_in[4];
    const float* g1   = (const float*)d_in[5];
    const float* be1  = (const float*)d_in[6];
    const float* W2   = (const float*)d_in[7];
    const float* b2   = (const float*)d_in[8];
    const float* g2   = (const float*)d_in[9];
    const float* be2  = (const float*)d_in[10];
    const float* Wc1  = (const float*)d_in[11];
    const float* bc1  = (const float*)d_in[12];
    const float* gc1  = (const float*)d_in[13];
    const float* bec1 = (const float*)d_in[14];
    const float* Wc2  = (const float*)d_in[15];
    const float* bc2  = (const float*)d_in[16];
    const float* gc2  = (const float*)d_in[17];
    const float* bec2 = (const float*)d_in[18];

    cudaFuncSetAttribute(k_graph1,   cudaFuncAttributeMaxDynamicSharedMemorySize, SM1_BYTES);
    cudaFuncSetAttribute(k_graph2_p, cudaFuncAttributeMaxDynamicSharedMemorySize, SM2_BYTES);

    k_graph1  <<<BG, 256, SM1_BYTES>>>(x, pos, W1, b1);
    k_red1    <<<128, 256>>>(g1, be1);
    k_fold2   <<<1, 128>>>(W2, b2);
    k_graph2_p<<<GRID2, 512, SM2_BYTES>>>();
    k_red2    <<<128, 256>>>(g2, be2);
    k_foldc1  <<<1, 256>>>(Wc1, bc1);
    k_cls1    <<<256, 256>>>();
    k_red3    <<<1, 256>>>(gc1, bec1, Wc2, bc2);
    k_z       <<<512, 256>>>();
    k_final   <<<1, 512>>>(gc2, bec2, (float*)d_out);
}

// round 11
// speedup vs baseline: 1.2646x; 1.0744x over previous
#include <cuda_runtime.h>
#include <cuda_bf16.h>
#include <math.h>

// ---------------------------------------------------------------------------
// PCN_37391985279556: B=4096 graphs x M=64 points, K=3-NN PointNet-ish net.
// All-FFMA2 implementation (tcgen05 unavailable in this harness).
//
//  k_graph1   : 512thr per-graph knn + U=x@W1[:59]+b1 (f32x2) + f32x2 edge
//               relu/K-max -> g_Hmax in TRANSPOSED [tile][kg][node][4]
//               layout + BN1 stat partials.
//  k_red1     : BN1 stats -> affine (a1,c1).
//  k_fold2    : fold BN1 into W2 -> g_W2p, b2'.
//  k_graph2_p : persistent ONE-GEMM [262144,128]@[128,128] f32x2 @512thr.
//               Transposed A-tiles: coalesced LDG + conflict-free STS
//               (no in-kernel transpose -> smem crossbar unbound).
//  k_red2 ... k_final : classifier tail (BN folds).
// ---------------------------------------------------------------------------

#define BG 4096
#define MP 64
#define KN 3
#define FXF 59
#define F1 128
#define F2 128
#define FC 256
#define NN (BG*MP)            // 262144 nodes
#define NE (NN*KN)            // 786432 edges
#define EPSB 1e-5f

// ---- device scratch ----
// g_Hmax layout: [tile=2048][kg=32][node=128][4] floats (134 MB)
__device__ float g_Hmax[(size_t)NN*F1];
__device__ float g_part1[BG*2*F1];
__device__ float g_ab1[2*F1];
__device__ float g_W2p[F1*F2];
__device__ float g_b2p[F2];
__device__ float g_Gsum[BG*F2];
__device__ float g_Qprt[BG*F2];
__device__ float g_ab2[2*F2];
__device__ float g_Wc1f[F2*FC];
__device__ float g_bc1f[FC];
__device__ float g_C1[(size_t)BG*FC];
__device__ float g_part3[256*2*FC];
__device__ float g_Wc2f[FC+1];
__device__ float g_z[BG];

// ---- packed f32x2 helpers ----
__device__ __forceinline__ unsigned long long pk2(float lo, float hi) {
    unsigned long long r;
    asm("mov.b64 %0,{%1,%2};" : "=l"(r) : "f"(lo), "f"(hi));
    return r;
}
__device__ __forceinline__ void upk2(unsigned long long v, float& lo, float& hi) {
    asm("mov.b64 {%0,%1},%2;" : "=f"(lo), "=f"(hi) : "l"(v));
}
__device__ __forceinline__ void fma2(unsigned long long& d,
                                     unsigned long long a, unsigned long long b) {
    asm("fma.rn.f32x2 %0,%1,%2,%0;" : "+l"(d) : "l"(a), "l"(b));
}

// ========================= k_graph1 (512 threads) ===========================
// smem floats:
// XS[59][68]@0 (4012), WS[62][128]@4012 (7936), US[64][128]@11948 (8192),
// BS@20140 (128), PS@20268 (192), KD@20460 (1536), KJ@21996 (1536,int),
// RELP@23532 (1152), SRS@24684 (1024), SRQ@25708 (1024), NBR@26732 (192,int)
// -> 26924 floats = 107696 B (2 blocks/SM)
#define XS_O 0
#define WS_O 4012
#define US_O 11948
#define BS_O 20140
#define PS_O 20268
#define KD_O 20460
#define KJ_O 21996
#define RELP_O 23532
#define SRS_O 24684
#define SRQ_O 25708
#define NBR_O 26732
#define SM1_FLOATS 26924
#define SM1_BYTES (SM1_FLOATS*4)

__global__ __launch_bounds__(512, 2)
void k_graph1(const float* __restrict__ x, const float* __restrict__ pos,
              const float* __restrict__ W1, const float* __restrict__ b1) {
    extern __shared__ float sm[];
    float* xsp  = sm + XS_O;
    float* ws   = sm + WS_O;
    float* us   = sm + US_O;
    float* bs   = sm + BS_O;
    float* ps   = sm + PS_O;
    float* kd   = sm + KD_O;
    int*   kj   = (int*)(sm + KJ_O);
    float* relp = sm + RELP_O;
    float* srS  = sm + SRS_O;
    float* srQ  = sm + SRQ_O;
    int*   nbr  = (int*)(sm + NBR_O);

    const int tid = threadIdx.x;
    const int g   = blockIdx.x;

    // --- loads ---
    const float* xg = x + (size_t)g * MP * FXF;
    for (int l = tid; l < MP * FXF; l += 512) {
        int i = l / FXF;
        int c = l - i * FXF;
        xsp[c * 68 + i] = xg[l];
    }
    for (int l = tid; l < 62 * F1; l += 512) ws[l] = W1[l];
    if (tid < F1) bs[tid] = b1[tid];
    if (tid < MP * 3) ps[tid] = pos[(size_t)g * MP * 3 + tid];
    __syncthreads();

    // --- knn partials: 8 threads per point, 8 candidates each ---
    {
        const int i   = tid & 63;
        const int blk = tid >> 6;            // 0..7
        float pix = ps[i*3], piy = ps[i*3+1], piz = ps[i*3+2];
        float d0 = 1e30f, d1 = 1e30f, d2 = 1e30f;
        int   j0 = 0, j1 = 0, j2 = 0;
#pragma unroll
        for (int jj = 0; jj < 8; jj++) {
            int j = blk * 8 + jj;
            float dx = ps[j*3]   - pix;
            float dy = ps[j*3+1] - piy;
            float dz = ps[j*3+2] - piz;
            float d = dx*dx + dy*dy + dz*dz;
            if (j == i) d = 1e30f;
            if (d < d0)      { d2=d1; j2=j1; d1=d0; j1=j0; d0=d; j0=j; }
            else if (d < d1) { d2=d1; j2=j1; d1=d; j1=j; }
            else if (d < d2) { d2=d; j2=j; }
        }
        kd[tid*3] = d0; kd[tid*3+1] = d1; kd[tid*3+2] = d2;
        kj[tid*3] = j0; kj[tid*3+1] = j1; kj[tid*3+2] = j2;
    }
    __syncthreads();

    // --- knn merge (tid<64), concurrent with GEMM on other warps ---
    if (tid < 64) {
        float d0 = 1e30f, d1 = 1e30f, d2 = 1e30f;
        int   j0 = 0, j1 = 0, j2 = 0;
#pragma unroll
        for (int b = 0; b < 8; b++) {
#pragma unroll
            for (int t = 0; t < 3; t++) {
                float d = kd[(b*64 + tid)*3 + t];
                int   j = kj[(b*64 + tid)*3 + t];
                if (d < d0)      { d2=d1; j2=j1; d1=d0; j1=j0; d0=d; j0=j; }
                else if (d < d1) { d2=d1; j2=j1; d1=d; j1=j; }
                else if (d < d2) { d2=d; j2=j; }
            }
        }
        nbr[tid*3] = j0; nbr[tid*3+1] = j1; nbr[tid*3+2] = j2;
    }

    // --- GEMM1: U[64,128] = x[64,59]@W1[0:59,:] + b1  (4 cols x 2 pairs) ---
    {
        const int f0 = (tid & 31) * 4;
        const int pb = (tid >> 5) * 2;          // pair base: 2 pairs = 4 nodes
        unsigned long long a[2][4];
#pragma unroll
        for (int p = 0; p < 2; p++)
#pragma unroll
            for (int c = 0; c < 4; c++) a[p][c] = 0ull;
#pragma unroll 4
        for (int c = 0; c < FXF; c++) {
            float4 w4 = *(const float4*)&ws[c * F1 + f0];
            unsigned long long w0 = pk2(w4.x, w4.x);
            unsigned long long w1 = pk2(w4.y, w4.y);
            unsigned long long w2 = pk2(w4.z, w4.z);
            unsigned long long w3 = pk2(w4.w, w4.w);
            ulonglong2 xA = *(const ulonglong2*)&xsp[c * 68 + pb * 2];
            fma2(a[0][0], xA.x, w0); fma2(a[0][1], xA.x, w1);
            fma2(a[0][2], xA.x, w2); fma2(a[0][3], xA.x, w3);
            fma2(a[1][0], xA.y, w0); fma2(a[1][1], xA.y, w1);
            fma2(a[1][2], xA.y, w2); fma2(a[1][3], xA.y, w3);
        }
        float4 b4 = *(const float4*)&bs[f0];
#pragma unroll
        for (int p = 0; p < 2; p++) {
            int n = (pb + p) * 2;
            float e0,o0,e1,o1,e2,o2,e3,o3;
            upk2(a[p][0], e0, o0); upk2(a[p][1], e1, o1);
            upk2(a[p][2], e2, o2); upk2(a[p][3], e3, o3);
            *(float4*)&us[n*F1 + f0] =
                make_float4(e0+b4.x, e1+b4.y, e2+b4.z, e3+b4.w);
            *(float4*)&us[(n+1)*F1 + f0] =
                make_float4(o0+b4.x, o1+b4.y, o2+b4.z, o3+b4.w);
        }
    }
    __syncthreads();

    // --- build duplicated rel pairs: relp[e][d] = float2(r,r), e=i*3+k ---
    if (tid < 192) {
        int i = tid / 3, k = tid - i * 3;
        int j = nbr[i*3 + k];
        float r0 = ps[j*3]   - ps[i*3];
        float r1 = ps[j*3+1] - ps[i*3+1];
        float r2 = ps[j*3+2] - ps[i*3+2];
        float2* rp = (float2*)relp + tid * 3;
        rp[0] = make_float2(r0, r0);
        rp[1] = make_float2(r1, r1);
        rp[2] = make_float2(r2, r2);
    }
    __syncthreads();

    // --- edges (f32x2): relu(U[j] + rel@W1[59:62]), K-max + BN1 partials ---
    // Hmax written TRANSPOSED: [tile=g>>1][kg=f>>2][node=(g&1)*64+i][f&3]
    {
        const int fp = tid & 63;        // feature pair -> f = 2*fp
        const int f  = fp * 2;
        const int gr = tid >> 6;        // eighth: 8 points each
        unsigned long long w59p = *(const unsigned long long*)&ws[59*F1 + f];
        unsigned long long w60p = *(const unsigned long long*)&ws[60*F1 + f];
        unsigned long long w61p = *(const unsigned long long*)&ws[61*F1 + f];
        float s0 = 0.f, q0 = 0.f, s1 = 0.f, q1 = 0.f;
        float* outT = g_Hmax + (size_t)(g >> 1) * 16384 + (g & 1) * 256
                    + (fp >> 1) * 512 + 2 * (fp & 1);
        for (int ii = 0; ii < 8; ii++) {
            int i = gr * 8 + ii;
            float hm0 = 0.f, hm1 = 0.f;
#pragma unroll
            for (int k = 0; k < KN; k++) {
                int e = i * 3 + k;
                int j = nbr[e];
                const unsigned long long* rp =
                    (const unsigned long long*)relp + (size_t)e * 3;
                unsigned long long v2 = *(const unsigned long long*)&us[j*F1 + f];
                fma2(v2, rp[0], w59p);
                fma2(v2, rp[1], w60p);
                fma2(v2, rp[2], w61p);
                float ev, ov;
                upk2(v2, ev, ov);
                ev = fmaxf(ev, 0.f); ov = fmaxf(ov, 0.f);
                s0 += ev; q0 = fmaf(ev, ev, q0);
                s1 += ov; q1 = fmaf(ov, ov, q1);
                hm0 = fmaxf(hm0, ev); hm1 = fmaxf(hm1, ov);
            }
            *(float2*)(outT + i * 4) = make_float2(hm0, hm1);
        }
        srS[gr * 128 + f] = s0; srS[gr * 128 + f + 1] = s1;
        srQ[gr * 128 + f] = q0; srQ[gr * 128 + f + 1] = q1;
    }
    __syncthreads();
    if (tid < F1) {
        float S = 0.f, Q = 0.f;
#pragma unroll
        for (int b = 0; b < 8; b++) {
            S += srS[b*128 + tid];
            Q += srQ[b*128 + tid];
        }
        g_part1[g*256 + tid]       = S;
        g_part1[g*256 + 128 + tid] = Q;
    }
}

__global__ void k_red1(const float* __restrict__ g1, const float* __restrict__ be1) {
    __shared__ float sS[256], sQ[256];
    const int f = blockIdx.x, tid = threadIdx.x;
    float s = 0.f, q = 0.f;
    for (int i = tid; i < BG; i += 256) {
        s += g_part1[i*256 + f];
        q += g_part1[i*256 + 128 + f];
    }
    sS[tid] = s; sQ[tid] = q; __syncthreads();
    for (int st = 128; st > 0; st >>= 1) {
        if (tid < st) { sS[tid] += sS[tid+st]; sQ[tid] += sQ[tid+st]; }
        __syncthreads();
    }
    if (tid == 0) {
        float inv = 1.f / (float)NE;
        float mu  = sS[0] * inv;
        float var = sQ[0] * inv - mu * mu;
        float a   = g1[f] * rsqrtf(var + EPSB);
        g_ab1[f]       = a;
        g_ab1[128 + f] = be1[f] - mu * a;
    }
}

__global__ void k_fold2(const float* __restrict__ W2, const float* __restrict__ b2) {
    __shared__ float sa[128], sc[128];
    const int tid = threadIdx.x;            // 128 threads
    sa[tid] = g_ab1[tid];
    sc[tid] = g_ab1[128 + tid];
    __syncthreads();
    float bacc = b2[tid];
    for (int c = 0; c < 128; c++) {
        float w = W2[c*128 + tid];
        g_W2p[c*128 + tid] = sa[c] * w;
        bacc += sc[c] * w;
    }
    g_b2p[tid] = bacc;
}

// ========================= k_graph2_p (persistent FFMA2 GEMM, 512 thr) ======
// A-source is pre-transposed -> staging is coalesced LDG + conflict-free STS.
// smem floats: WS2[128][128]@0, HT[128][132]@16384,
// SS[16][128]@33280, SQ[16][128]@35328  -> 37376 floats = 149504 B
#define WS2_O 0
#define HT_O  16384
#define HT_STRIDE 132
#define SS_O 33280
#define SQ_O 35328
#define SM2_FLOATS 37376
#define SM2_BYTES (SM2_FLOATS*4)
#define NT2 2048
#define GRID2 148

__global__ __launch_bounds__(512, 1)
void k_graph2_p() {
    extern __shared__ float sm[];
    float* ws2  = sm + WS2_O;
    float* hT   = sm + HT_O;
    float* sS   = sm + SS_O;
    float* sQ   = sm + SQ_O;

    const int tid = threadIdx.x;
    const int wid = tid >> 5;

    // one-time weight residency
    for (int i = tid; i < 4096; i += 512)
        *(float4*)&ws2[i*4] = *(const float4*)&g_W2p[i*4];

    const int f0 = (tid & 31) * 4;
    const int pb = wid * 4;                 // 4 pairs = 8 nodes per warp
    const float bb0 = g_b2p[f0], bb1 = g_b2p[f0+1],
                bb2 = g_b2p[f0+2], bb3 = g_b2p[f0+3];

    // staging indices: idx = tid + u*512 over 4096 float4s of a tile
    // kg = idx>>7 (k-group), n = idx&127 (node)
    const int nstage = tid & 127;
    // prefetch registers
    float4 pre[8];
    int tile = blockIdx.x;
    {
        const float4* src = (const float4*)g_Hmax + (size_t)tile * 4096;
#pragma unroll
        for (int u = 0; u < 8; u++)
            pre[u] = src[tid + u * 512];
    }

    for (; tile < NT2; tile += GRID2) {
        __syncthreads();                    // hT free (prev epilogue done)
        // commit prefetched A tile (already k-major): conflict-free stores
#pragma unroll
        for (int u = 0; u < 8; u++) {
            int kg = (tid + u * 512) >> 7;
            float4 v = pre[u];
            float* dst = &hT[(4*kg) * HT_STRIDE + nstage];
            dst[0]             = v.x;
            dst[HT_STRIDE]     = v.y;
            dst[2*HT_STRIDE]   = v.z;
            dst[3*HT_STRIDE]   = v.w;
        }
        __syncthreads();

        // issue next tile's LDGs now; they complete during the GEMM below
        int ntile = tile + GRID2;
        if (ntile < NT2) {
            const float4* src = (const float4*)g_Hmax + (size_t)ntile * 4096;
#pragma unroll
            for (int u = 0; u < 8; u++)
                pre[u] = src[tid + u * 512];
        }

        // GEMM: 4 cols x 4 pairs (8 nodes) per thread
        unsigned long long a[4][4];
#pragma unroll
        for (int p = 0; p < 4; p++)
#pragma unroll
            for (int c = 0; c < 4; c++) a[p][c] = 0ull;
#pragma unroll 4
        for (int c = 0; c < F1; c++) {
            float4 w4 = *(const float4*)&ws2[c * F2 + f0];
            unsigned long long w0 = pk2(w4.x, w4.x);
            unsigned long long w1 = pk2(w4.y, w4.y);
            unsigned long long w2 = pk2(w4.z, w4.z);
            unsigned long long w3 = pk2(w4.w, w4.w);
            const float* xr = &hT[c * HT_STRIDE + pb * 2];
            ulonglong2 xA = *(const ulonglong2*)(xr);
            ulonglong2 xB = *(const ulonglong2*)(xr + 4);
            fma2(a[0][0], xA.x, w0); fma2(a[0][1], xA.x, w1);
            fma2(a[0][2], xA.x, w2); fma2(a[0][3], xA.x, w3);
            fma2(a[1][0], xA.y, w0); fma2(a[1][1], xA.y, w1);
            fma2(a[1][2], xA.y, w2); fma2(a[1][3], xA.y, w3);
            fma2(a[2][0], xB.x, w0); fma2(a[2][1], xB.x, w1);
            fma2(a[2][2], xB.x, w2); fma2(a[2][3], xB.x, w3);
            fma2(a[3][0], xB.y, w0); fma2(a[3][1], xB.y, w1);
            fma2(a[3][2], xB.y, w2); fma2(a[3][3], xB.y, w3);
        }

        // epilogue: bias + relu, per-thread column sums over its 8 nodes
        float sv0=0.f,sv1=0.f,sv2=0.f,sv3=0.f;
        float qv0=0.f,qv1=0.f,qv2=0.f,qv3=0.f;
#pragma unroll
        for (int p = 0; p < 4; p++) {
            float e, o, v;
            upk2(a[p][0], e, o);
            v = fmaxf(e + bb0, 0.f); sv0 += v; qv0 += v*v;
            v = fmaxf(o + bb0, 0.f); sv0 += v; qv0 += v*v;
            upk2(a[p][1], e, o);
            v = fmaxf(e + bb1, 0.f); sv1 += v; qv1 += v*v;
            v = fmaxf(o + bb1, 0.f); sv1 += v; qv1 += v*v;
            upk2(a[p][2], e, o);
            v = fmaxf(e + bb2, 0.f); sv2 += v; qv2 += v*v;
            v = fmaxf(o + bb2, 0.f); sv2 += v; qv2 += v*v;
            upk2(a[p][3], e, o);
            v = fmaxf(e + bb3, 0.f); sv3 += v; qv3 += v*v;
            v = fmaxf(o + bb3, 0.f); sv3 += v; qv3 += v*v;
        }
        sS[wid*128 + f0] = sv0; sS[wid*128 + f0+1] = sv1;
        sS[wid*128 + f0+2] = sv2; sS[wid*128 + f0+3] = sv3;
        sQ[wid*128 + f0] = qv0; sQ[wid*128 + f0+1] = qv1;
        sQ[wid*128 + f0+2] = qv2; sQ[wid*128 + f0+3] = qv3;
        __syncthreads();
        if (tid < 256) {
            int col  = tid & 127;
            int gsel = tid >> 7;            // warps 0-7: nodes 0-63 (graph even)
            int r0 = gsel * 8;
            float S = 0.f, Q = 0.f;
#pragma unroll
            for (int w = 0; w < 8; w++) {
                S += sS[(r0 + w)*128 + col];
                Q += sQ[(r0 + w)*128 + col];
            }
            int g = tile * 2 + gsel;
            g_Gsum[g*128 + col] = S;
            g_Qprt[g*128 + col] = Q;
        }
    }
}

// ========================= classifier tail ==================================
__global__ void k_red2(const float* __restrict__ g2, const float* __restrict__ be2) {
    __shared__ float sS[256], sQ[256];
    const int f = blockIdx.x, tid = threadIdx.x;
    float s = 0.f, q = 0.f;
    for (int i = tid; i < BG; i += 256) {
        s += g_Gsum[i*F2 + f];
        q += g_Qprt[i*F2 + f];
    }
    sS[tid] = s; sQ[tid] = q; __syncthreads();
    for (int st = 128; st > 0; st >>= 1) {
        if (tid < st) { sS[tid] += sS[tid+st]; sQ[tid] += sQ[tid+st]; }
        __syncthreads();
    }
    if (tid == 0) {
        float inv = 1.f / (float)NN;
        float mu  = sS[0] * inv;
        float var = sQ[0] * inv - mu * mu;
        float a   = g2[f] * rsqrtf(var + EPSB);
        g_ab2[f]       = a;
        g_ab2[128 + f] = be2[f] - mu * a;
    }
}

__global__ void k_foldc1(const float* __restrict__ Wc1, const float* __restrict__ bc1) {
    __shared__ float sa[128], sc[128];
    const int tid = threadIdx.x;            // 256 threads
    if (tid < 128) {
        sa[tid] = g_ab2[tid] * (1.f / 64.f);
        sc[tid] = g_ab2[128 + tid];
    }
    __syncthreads();
    float bacc = bc1[tid];
    for (int c = 0; c < 128; c++) {
        float w = Wc1[c*256 + tid];
        g_Wc1f[c*256 + tid] = sa[c] * w;
        bacc += sc[c] * w;
    }
    g_bc1f[tid] = bacc;
}

__global__ __launch_bounds__(256)
void k_cls1() {
    __shared__ float gs[16 * 128];
    const int tid = threadIdx.x;
    const int blk = blockIdx.x;
    const float* G = g_Gsum + (size_t)blk * 16 * F2;
    for (int l = tid; l < 16 * 128; l += 256) gs[l] = G[l];
    __syncthreads();
    float acc[16];
    const float bb = g_bc1f[tid];
#pragma unroll
    for (int r = 0; r < 16; r++) acc[r] = bb;
    for (int c = 0; c < 128; c++) {
        float w = g_Wc1f[c*256 + tid];
#pragma unroll
        for (int r = 0; r < 16; r++) acc[r] += gs[r*128 + c] * w;
    }
    float s = 0.f, q = 0.f;
#pragma unroll
    for (int r = 0; r < 16; r++) {
        float v = fmaxf(acc[r], 0.f);
        g_C1[((size_t)blk * 16 + r) * 256 + tid] = v;
        s += v; q += v * v;
    }
    g_part3[blk*512 + tid]       = s;
    g_part3[blk*512 + 256 + tid] = q;
}

__global__ void k_red3(const float* __restrict__ gc1, const float* __restrict__ bec1,
                       const float* __restrict__ Wc2, const float* __restrict__ bc2) {
    __shared__ float red[256];
    const int tid = threadIdx.x;
    float s = 0.f, q = 0.f;
    for (int i = 0; i < 256; i++) {
        s += g_part3[i*512 + tid];
        q += g_part3[i*512 + 256 + tid];
    }
    float inv = 1.f / (float)BG;
    float mu  = s * inv;
    float var = q * inv - mu * mu;
    float a   = gc1[tid] * rsqrtf(var + EPSB);
    float c   = bec1[tid] - mu * a;
    float w   = Wc2[tid];
    g_Wc2f[tid] = a * w;
    red[tid] = c * w;
    __syncthreads();
    for (int st = 128; st > 0; st >>= 1) {
        if (tid < st) red[tid] += red[tid + st];
        __syncthreads();
    }
    if (tid == 0) g_Wc2f[256] = bc2[0] + red[0];
}

__global__ void k_z() {
    const int tid  = threadIdx.x;
    const int w    = tid >> 5;
    const int lane = tid & 31;
    const int r    = blockIdx.x * 8 + w;
    const float* row = g_C1 + (size_t)r * 256;
    float acc = 0.f;
#pragma unroll
    for (int t = 0; t < 8; t++) {
        int idx = lane + t * 32;
        acc += row[idx] * g_Wc2f[idx];
    }
    for (int off = 16; off; off >>= 1)
        acc += __shfl_down_sync(0xffffffffu, acc, off);
    if (lane == 0) g_z[r] = fmaxf(acc + g_Wc2f[256], 0.f);
}

__global__ void k_final(const float* __restrict__ gc2, const float* __restrict__ bec2,
                        float* __restrict__ out) {
    __shared__ float sS[512], sQ[512];
    const int tid = threadIdx.x;
    float s = 0.f, q = 0.f;
    float zv[8];
#pragma unroll
    for (int t = 0; t < 8; t++) {
        float v = g_z[tid + 512 * t];
        zv[t] = v; s += v; q += v * v;
    }
    sS[tid] = s; sQ[tid] = q; __syncthreads();
    for (int st = 256; st > 0; st >>= 1) {
        if (tid < st) { sS[tid] += sS[tid+st]; sQ[tid] += sQ[tid+st]; }
        __syncthreads();
    }
    float inv = 1.f / (float)BG;
    float mu  = sS[0] * inv;
    float var = sQ[0] * inv - mu * mu;
    float a   = gc2[0] * rsqrtf(var + EPSB);
    float b   = bec2[0];
#pragma unroll
    for (int t = 0; t < 8; t++) {
        float tt = a * (zv[t] - mu) + b;
        out[tid + 512 * t] = 1.f / (1.f + expf(-tt));
    }
}

extern "C" void kernel_launch(void* const* d_in, const int* in_sizes, int n_in,
                              void* d_out, int out_size) {
    const float* x    = (const float*)d_in[0];
    const float* pos  = (const float*)d_in[1];
    const float* W1   = (const float*)d_in[3];
    const float* b1   = (const float*)d_in[4];
    const float* g1   = (const float*)d_in[5];
    const float* be1  = (const float*)d_in[6];
    const float* W2   = (const float*)d_in[7];
    const float* b2   = (const float*)d_in[8];
    const float* g2   = (const float*)d_in[9];
    const float* be2  = (const float*)d_in[10];
    const float* Wc1  = (const float*)d_in[11];
    const float* bc1  = (const float*)d_in[12];
    const float* gc1  = (const float*)d_in[13];
    const float* bec1 = (const float*)d_in[14];
    const float* Wc2  = (const float*)d_in[15];
    const float* bc2  = (const float*)d_in[16];
    const float* gc2  = (const float*)d_in[17];
    const float* bec2 = (const float*)d_in[18];

    cudaFuncSetAttribute(k_graph1,   cudaFuncAttributeMaxDynamicSharedMemorySize, SM1_BYTES);
    cudaFuncSetAttribute(k_graph2_p, cudaFuncAttributeMaxDynamicSharedMemorySize, SM2_BYTES);

    k_graph1  <<<BG, 512, SM1_BYTES>>>(x, pos, W1, b1);
    k_red1    <<<128, 256>>>(g1, be1);
    k_fold2   <<<1, 128>>>(W2, b2);
    k_graph2_p<<<GRID2, 512, SM2_BYTES>>>();
    k_red2    <<<128, 256>>>(g2, be2);
    k_foldc1  <<<1, 256>>>(Wc1, bc1);
    k_cls1    <<<256, 256>>>();
    k_red3    <<<1, 256>>>(gc1, bec1, Wc2, bc2);
    k_z       <<<512, 256>>>();
    k_final   <<<1, 512>>>(gc2, bec2, (float*)d_out);
}

// round 16
// speedup vs baseline: 1.4942x; 1.1815x over previous
#include <cuda_runtime.h>
#include <cuda_bf16.h>
#include <math.h>

// ---------------------------------------------------------------------------
// PCN_37391985279556: B=4096 graphs x M=64 points, K=3-NN PointNet-ish net.
// All-FFMA2 implementation (tcgen05 unavailable in this harness).
//
//  k_xT     : repack x -> transposed padded tiles [2048][15][128][4].
//  k_knn    : per-graph knn -> g_nbr + duplicated rel pairs g_relp (PACKED:
//             1152 floats per graph).
//  k_ue_p   : persistent fused U-GEMM [262144,59]@[59,128] (f32x2, W1
//             resident, xT prefetched) + in-smem U + edge relu/K-max ->
//             g_Hmax (transposed tiles) + BN1 stat partials.
//  k_red1   : BN1 stats -> affine (a1,c1).
//  k_fold2  : fold BN1 into W2 -> g_W2p, b2'.
//  k_graph2_p: persistent ONE-GEMM [262144,128]@[128,128] f32x2 (at its
//             RF-bank rt=3 roofline).
//  k_red2 ... k_final : classifier tail (BN folds).
// ---------------------------------------------------------------------------

#define BG 4096
#define MP 64
#define KN 3
#define FXF 59
#define F1 128
#define F2 128
#define FC 256
#define NN (BG*MP)            // 262144 nodes
#define NE (NN*KN)            // 786432 edges
#define EPSB 1e-5f

// ---- device scratch ----
// g_Hmax layout: [tile=2048][kg=32][node=128][4] floats (134 MB)
__device__ float g_Hmax[(size_t)NN*F1];
__device__ float g_xT[(size_t)2048*7680];   // [tile][kg=15][node=128][4] 63MB
__device__ int   g_nbr[BG*192];             // per-graph local knn indices
__device__ float g_relp[(size_t)BG*1152];   // PACKED [g][64 pts][9 float2]
__device__ float g_part1[BG*2*F1];
__device__ float g_ab1[2*F1];
__device__ float g_W2p[F1*F2];
__device__ float g_b2p[F2];
__device__ float g_Gsum[BG*F2];
__device__ float g_Qprt[BG*F2];
__device__ float g_ab2[2*F2];
__device__ float g_Wc1f[F2*FC];
__device__ float g_bc1f[FC];
__device__ float g_C1[(size_t)BG*FC];
__device__ float g_part3[256*2*FC];
__device__ float g_Wc2f[FC+1];
__device__ float g_z[BG];

// ---- packed f32x2 helpers ----
__device__ __forceinline__ unsigned long long pk2(float lo, float hi) {
    unsigned long long r;
    asm("mov.b64 %0,{%1,%2};" : "=l"(r) : "f"(lo), "f"(hi));
    return r;
}
__device__ __forceinline__ void upk2(unsigned long long v, float& lo, float& hi) {
    asm("mov.b64 {%0,%1},%2;" : "=f"(lo), "=f"(hi) : "l"(v));
}
__device__ __forceinline__ void fma2(unsigned long long& d,
                                     unsigned long long a, unsigned long long b) {
    asm("fma.rn.f32x2 %0,%1,%2,%0;" : "+l"(d) : "l"(a), "l"(b));
}

// ========================= k_xT: repack x ===================================
__global__ __launch_bounds__(256)
void k_xT(const float* __restrict__ x) {
    __shared__ float xs[7552];              // 128 rows x 59
    const int tile = blockIdx.x, tid = threadIdx.x;
    const float4* src = (const float4*)(x + (size_t)tile * 7552);
    for (int u = tid; u < 1888; u += 256)
        ((float4*)xs)[u] = src[u];
    __syncthreads();
    float4* dst = (float4*)(g_xT + (size_t)tile * 7680);
    for (int idx = tid; idx < 1920; idx += 256) {
        int kg = idx >> 7, nd = idx & 127;
        int c = kg * 4;
        const float* r = xs + nd * 59 + c;
        float4 v;
        v.x = r[0];
        v.y = r[1];
        v.z = r[2];
        v.w = (c + 3 < FXF) ? r[3] : 0.f;   // pad col 59 with 0
        dst[idx] = v;
    }
}

// ========================= k_knn: per-graph knn + rel ======================
__global__ __launch_bounds__(64)
void k_knn(const float* __restrict__ pos) {
    __shared__ float ps[192];
    const int g = blockIdx.x, i = threadIdx.x;
    ps[i]       = pos[(size_t)g*192 + i];
    ps[64 + i]  = pos[(size_t)g*192 + 64 + i];
    ps[128 + i] = pos[(size_t)g*192 + 128 + i];
    __syncthreads();

    float pix = ps[i*3], piy = ps[i*3+1], piz = ps[i*3+2];
    float d0 = 1e30f, d1 = 1e30f, d2 = 1e30f;
    int   j0 = 0, j1 = 0, j2 = 0;
    for (int j = 0; j < MP; j++) {
        float dx = ps[j*3]   - pix;
        float dy = ps[j*3+1] - piy;
        float dz = ps[j*3+2] - piz;
        float d = dx*dx + dy*dy + dz*dz;
        if (j == i) d = 1e30f;
        if (d < d0)      { d2=d1; j2=j1; d1=d0; j1=j0; d0=d; j0=j; }
        else if (d < d1) { d2=d1; j2=j1; d1=d; j1=j; }
        else if (d < d2) { d2=d; j2=j; }
    }
    int* nb = g_nbr + (size_t)g*192 + i*3;
    nb[0] = j0; nb[1] = j1; nb[2] = j2;
    // PACKED: 1152 floats (= 576 float2) per graph
    float2* rp = (float2*)(g_relp + (size_t)g*1152) + i*9;
    int js[3] = {j0, j1, j2};
#pragma unroll
    for (int k = 0; k < 3; k++) {
        int j = js[k];
        float r0 = ps[j*3]   - pix;
        float r1 = ps[j*3+1] - piy;
        float r2 = ps[j*3+2] - piz;
        rp[k*3 + 0] = make_float2(r0, r0);
        rp[k*3 + 1] = make_float2(r1, r1);
        rp[k*3 + 2] = make_float2(r2, r2);
    }
}

// ========================= k_ue_p: persistent U-GEMM + edges ================
// smem floats: WS[62][128]@0 (7936), XT[60][132]@7936 (7920),
// US[128][128]@15856 (16384), NB@32240 (384,int), RP@32624 (2304),
// S1@34928 (1024), Q1@35952 (1024) -> 36976 floats = 147904 B
#define UE_WS 0
#define UE_XT 7936
#define UE_US 15856
#define UE_NB 32240
#define UE_RP 32624
#define UE_S1 34928
#define UE_Q1 35952
#define UE_FLOATS 36976
#define UE_BYTES (UE_FLOATS*4)
#define XT_STRIDE 132
#define NTU 2048
#define GRIDU 148

__global__ __launch_bounds__(512, 1)
void k_ue_p(const float* __restrict__ W1, const float* __restrict__ b1) {
    extern __shared__ float sm[];
    float* ws  = sm + UE_WS;
    float* xTs = sm + UE_XT;
    float* us  = sm + UE_US;
    int*   nbs = (int*)(sm + UE_NB);
    float* rps = sm + UE_RP;
    float* sS  = sm + UE_S1;
    float* sQ  = sm + UE_Q1;

    const int tid = threadIdx.x;
    const int wid = tid >> 5;

    // one-time W1 residency (62 rows incl. rel weights 59-61)
    for (int i = tid; i < 1984; i += 512)
        ((float4*)ws)[i] = ((const float4*)W1)[i];

    const int f0 = (tid & 31) * 4;
    const int pb = wid * 4;                 // 4 node-pairs = 8 nodes per warp
    const float bb0 = b1[f0], bb1 = b1[f0+1],
                bb2 = b1[f0+2], bb3 = b1[f0+3];
    const int fp  = tid & 63;               // edge-phase feature pair
    const int fe  = fp * 2;
    const int grp = tid >> 6;               // 8 groups x 16 points

    // prefetch regs
    float4 pre[4];
    float4 rpre[2];
    int    npre = 0;
    int tile = blockIdx.x;
    {
        const float4* srcx = (const float4*)g_xT + (size_t)tile * 1920;
#pragma unroll
        for (int u = 0; u < 3; u++) pre[u] = srcx[tid + u * 512];
        if (tid < 384) { pre[3] = srcx[tid + 1536]; npre = g_nbr[tile*384 + tid]; }
        const float4* srcr = (const float4*)g_relp + (size_t)tile * 576;
        rpre[0] = srcr[tid];
        if (tid < 64) rpre[1] = srcr[512 + tid];
    }

    for (; tile < NTU; tile += GRIDU) {
        __syncthreads();                    // buffers free (prev edge done)
        // ---- commit prefetched tile ----
#pragma unroll
        for (int u = 0; u < 4; u++) {
            int idx = tid + u * 512;
            if (u < 3 || tid < 384) {
                int kg = idx >> 7, nd = idx & 127;
                float* dst = &xTs[(4*kg) * XT_STRIDE + nd];
                float4 v = pre[u];
                dst[0]            = v.x;
                dst[XT_STRIDE]    = v.y;
                dst[2*XT_STRIDE]  = v.z;
                dst[3*XT_STRIDE]  = v.w;
            }
        }
        if (tid < 384) nbs[tid] = npre;
        ((float4*)rps)[tid] = rpre[0];
        if (tid < 64) ((float4*)rps)[512 + tid] = rpre[1];
        __syncthreads();

        // ---- prefetch next tile (completes during GEMM) ----
        int nt = tile + GRIDU;
        if (nt < NTU) {
            const float4* srcx = (const float4*)g_xT + (size_t)nt * 1920;
#pragma unroll
            for (int u = 0; u < 3; u++) pre[u] = srcx[tid + u * 512];
            if (tid < 384) { pre[3] = srcx[tid + 1536]; npre = g_nbr[nt*384 + tid]; }
            const float4* srcr = (const float4*)g_relp + (size_t)nt * 576;
            rpre[0] = srcr[tid];
            if (tid < 64) rpre[1] = srcr[512 + tid];
        }

        // ---- GEMM: U[128,128] = xT^T @ W1[0:59] (60 iters, pad row = 0) ---
        unsigned long long a[4][4];
#pragma unroll
        for (int p = 0; p < 4; p++)
#pragma unroll
            for (int c = 0; c < 4; c++) a[p][c] = 0ull;
#pragma unroll 4
        for (int c = 0; c < 60; c++) {
            float4 w4 = *(const float4*)&ws[c * F1 + f0];
            unsigned long long w0 = pk2(w4.x, w4.x);
            unsigned long long w1 = pk2(w4.y, w4.y);
            unsigned long long w2 = pk2(w4.z, w4.z);
            unsigned long long w3 = pk2(w4.w, w4.w);
            const float* xr = &xTs[c * XT_STRIDE + pb * 2];
            ulonglong2 xA = *(const ulonglong2*)(xr);
            ulonglong2 xB = *(const ulonglong2*)(xr + 4);
            fma2(a[0][0], xA.x, w0); fma2(a[0][1], xA.x, w1);
            fma2(a[0][2], xA.x, w2); fma2(a[0][3], xA.x, w3);
            fma2(a[1][0], xA.y, w0); fma2(a[1][1], xA.y, w1);
            fma2(a[1][2], xA.y, w2); fma2(a[1][3], xA.y, w3);
            fma2(a[2][0], xB.x, w0); fma2(a[2][1], xB.x, w1);
            fma2(a[2][2], xB.x, w2); fma2(a[2][3], xB.x, w3);
            fma2(a[3][0], xB.y, w0); fma2(a[3][1], xB.y, w1);
            fma2(a[3][2], xB.y, w2); fma2(a[3][3], xB.y, w3);
        }
        // store U + b1 to smem (conflict-free float4)
#pragma unroll
        for (int p = 0; p < 4; p++) {
            int n = pb * 2 + p * 2;
            float e0,o0,e1,o1,e2,o2,e3,o3;
            upk2(a[p][0], e0, o0); upk2(a[p][1], e1, o1);
            upk2(a[p][2], e2, o2); upk2(a[p][3], e3, o3);
            *(float4*)&us[n*F1 + f0] =
                make_float4(e0+bb0, e1+bb1, e2+bb2, e3+bb3);
            *(float4*)&us[(n+1)*F1 + f0] =
                make_float4(o0+bb0, o1+bb1, o2+bb2, o3+bb3);
        }
        __syncthreads();

        // ---- edge phase: relu(U[j] + rel@W1[59:62]), K-max, BN1 stats ----
        {
            unsigned long long w59p = *(const unsigned long long*)&ws[59*F1 + fe];
            unsigned long long w60p = *(const unsigned long long*)&ws[60*F1 + fe];
            unsigned long long w61p = *(const unsigned long long*)&ws[61*F1 + fe];
            float s0 = 0.f, q0 = 0.f, s1 = 0.f, q1 = 0.f;
            float* outT = g_Hmax + (size_t)tile * 16384
                        + (fp >> 1) * 512 + 2 * (fp & 1);
            for (int ii = 0; ii < 16; ii++) {
                int i  = grp * 16 + ii;     // tile-local node 0..127
                int gg = i >> 6;            // graph within tile
                int il = i & 63;
                const int* nb = nbs + gg * 192 + il * 3;
                const unsigned long long* rp =
                    (const unsigned long long*)rps + (size_t)gg * 576 + il * 9;
                float hm0 = 0.f, hm1 = 0.f;
#pragma unroll
                for (int k = 0; k < KN; k++) {
                    int j = nb[k];
                    unsigned long long v2 =
                        *(const unsigned long long*)&us[(gg*64 + j)*F1 + fe];
                    fma2(v2, rp[k*3 + 0], w59p);
                    fma2(v2, rp[k*3 + 1], w60p);
                    fma2(v2, rp[k*3 + 2], w61p);
                    float ev, ov;
                    upk2(v2, ev, ov);
                    ev = fmaxf(ev, 0.f); ov = fmaxf(ov, 0.f);
                    s0 += ev; q0 = fmaf(ev, ev, q0);
                    s1 += ov; q1 = fmaf(ov, ov, q1);
                    hm0 = fmaxf(hm0, ev); hm1 = fmaxf(hm1, ov);
                }
                *(float2*)(outT + i * 4) = make_float2(hm0, hm1);
            }
            sS[grp*128 + fe] = s0; sS[grp*128 + fe + 1] = s1;
            sQ[grp*128 + fe] = q0; sQ[grp*128 + fe + 1] = q1;
        }
        __syncthreads();
        if (tid < 256) {
            int col  = tid & 127;
            int gsel = tid >> 7;
            int r0 = gsel * 4;
            float S = sS[(r0  )*128+col] + sS[(r0+1)*128+col]
                    + sS[(r0+2)*128+col] + sS[(r0+3)*128+col];
            float Q = sQ[(r0  )*128+col] + sQ[(r0+1)*128+col]
                    + sQ[(r0+2)*128+col] + sQ[(r0+3)*128+col];
            int g = tile * 2 + gsel;
            g_part1[g*256 + col]       = S;
            g_part1[g*256 + 128 + col] = Q;
        }
    }
}

__global__ void k_red1(const float* __restrict__ g1, const float* __restrict__ be1) {
    __shared__ float sS[256], sQ[256];
    const int f = blockIdx.x, tid = threadIdx.x;
    float s = 0.f, q = 0.f;
    for (int i = tid; i < BG; i += 256) {
        s += g_part1[i*256 + f];
        q += g_part1[i*256 + 128 + f];
    }
    sS[tid] = s; sQ[tid] = q; __syncthreads();
    for (int st = 128; st > 0; st >>= 1) {
        if (tid < st) { sS[tid] += sS[tid+st]; sQ[tid] += sQ[tid+st]; }
        __syncthreads();
    }
    if (tid == 0) {
        float inv = 1.f / (float)NE;
        float mu  = sS[0] * inv;
        float var = sQ[0] * inv - mu * mu;
        float a   = g1[f] * rsqrtf(var + EPSB);
        g_ab1[f]       = a;
        g_ab1[128 + f] = be1[f] - mu * a;
    }
}

__global__ void k_fold2(const float* __restrict__ W2, const float* __restrict__ b2) {
    __shared__ float sa[128], sc[128];
    const int tid = threadIdx.x;            // 128 threads
    sa[tid] = g_ab1[tid];
    sc[tid] = g_ab1[128 + tid];
    __syncthreads();
    float bacc = b2[tid];
    for (int c = 0; c < 128; c++) {
        float w = W2[c*128 + tid];
        g_W2p[c*128 + tid] = sa[c] * w;
        bacc += sc[c] * w;
    }
    g_b2p[tid] = bacc;
}

// ========================= k_graph2_p (persistent FFMA2 GEMM, 512 thr) ======
#define WS2_O 0
#define HT_O  16384
#define HT_STRIDE 132
#define SS_O 33280
#define SQ_O 35328
#define SM2_FLOATS 37376
#define SM2_BYTES (SM2_FLOATS*4)
#define NT2 2048
#define GRID2 148

__global__ __launch_bounds__(512, 1)
void k_graph2_p() {
    extern __shared__ float sm[];
    float* ws2  = sm + WS2_O;
    float* hT   = sm + HT_O;
    float* sS   = sm + SS_O;
    float* sQ   = sm + SQ_O;

    const int tid = threadIdx.x;
    const int wid = tid >> 5;

    for (int i = tid; i < 4096; i += 512)
        *(float4*)&ws2[i*4] = *(const float4*)&g_W2p[i*4];

    const int f0 = (tid & 31) * 4;
    const int pb = wid * 4;
    const float bb0 = g_b2p[f0], bb1 = g_b2p[f0+1],
                bb2 = g_b2p[f0+2], bb3 = g_b2p[f0+3];

    const int nstage = tid & 127;
    float4 pre[8];
    int tile = blockIdx.x;
    {
        const float4* src = (const float4*)g_Hmax + (size_t)tile * 4096;
#pragma unroll
        for (int u = 0; u < 8; u++)
            pre[u] = src[tid + u * 512];
    }

    for (; tile < NT2; tile += GRID2) {
        __syncthreads();
#pragma unroll
        for (int u = 0; u < 8; u++) {
            int kg = (tid + u * 512) >> 7;
            float4 v = pre[u];
            float* dst = &hT[(4*kg) * HT_STRIDE + nstage];
            dst[0]             = v.x;
            dst[HT_STRIDE]     = v.y;
            dst[2*HT_STRIDE]   = v.z;
            dst[3*HT_STRIDE]   = v.w;
        }
        __syncthreads();

        int ntile = tile + GRID2;
        if (ntile < NT2) {
            const float4* src = (const float4*)g_Hmax + (size_t)ntile * 4096;
#pragma unroll
            for (int u = 0; u < 8; u++)
                pre[u] = src[tid + u * 512];
        }

        unsigned long long a[4][4];
#pragma unroll
        for (int p = 0; p < 4; p++)
#pragma unroll
            for (int c = 0; c < 4; c++) a[p][c] = 0ull;
#pragma unroll 4
        for (int c = 0; c < F1; c++) {
            float4 w4 = *(const float4*)&ws2[c * F2 + f0];
            unsigned long long w0 = pk2(w4.x, w4.x);
            unsigned long long w1 = pk2(w4.y, w4.y);
            unsigned long long w2 = pk2(w4.z, w4.z);
            unsigned long long w3 = pk2(w4.w, w4.w);
            const float* xr = &hT[c * HT_STRIDE + pb * 2];
            ulonglong2 xA = *(const ulonglong2*)(xr);
            ulonglong2 xB = *(const ulonglong2*)(xr + 4);
            fma2(a[0][0], xA.x, w0); fma2(a[0][1], xA.x, w1);
            fma2(a[0][2], xA.x, w2); fma2(a[0][3], xA.x, w3);
            fma2(a[1][0], xA.y, w0); fma2(a[1][1], xA.y, w1);
            fma2(a[1][2], xA.y, w2); fma2(a[1][3], xA.y, w3);
            fma2(a[2][0], xB.x, w0); fma2(a[2][1], xB.x, w1);
            fma2(a[2][2], xB.x, w2); fma2(a[2][3], xB.x, w3);
            fma2(a[3][0], xB.y, w0); fma2(a[3][1], xB.y, w1);
            fma2(a[3][2], xB.y, w2); fma2(a[3][3], xB.y, w3);
        }

        float sv0=0.f,sv1=0.f,sv2=0.f,sv3=0.f;
        float qv0=0.f,qv1=0.f,qv2=0.f,qv3=0.f;
#pragma unroll
        for (int p = 0; p < 4; p++) {
            float e, o, v;
            upk2(a[p][0], e, o);
            v = fmaxf(e + bb0, 0.f); sv0 += v; qv0 += v*v;
            v = fmaxf(o + bb0, 0.f); sv0 += v; qv0 += v*v;
            upk2(a[p][1], e, o);
            v = fmaxf(e + bb1, 0.f); sv1 += v; qv1 += v*v;
            v = fmaxf(o + bb1, 0.f); sv1 += v; qv1 += v*v;
            upk2(a[p][2], e, o);
            v = fmaxf(e + bb2, 0.f); sv2 += v; qv2 += v*v;
            v = fmaxf(o + bb2, 0.f); sv2 += v; qv2 += v*v;
            upk2(a[p][3], e, o);
            v = fmaxf(e + bb3, 0.f); sv3 += v; qv3 += v*v;
            v = fmaxf(o + bb3, 0.f); sv3 += v; qv3 += v*v;
        }
        sS[wid*128 + f0] = sv0; sS[wid*128 + f0+1] = sv1;
        sS[wid*128 + f0+2] = sv2; sS[wid*128 + f0+3] = sv3;
        sQ[wid*128 + f0] = qv0; sQ[wid*128 + f0+1] = qv1;
        sQ[wid*128 + f0+2] = qv2; sQ[wid*128 + f0+3] = qv3;
        __syncthreads();
        if (tid < 256) {
            int col  = tid & 127;
            int gsel = tid >> 7;
            int r0 = gsel * 8;
            float S = 0.f, Q = 0.f;
#pragma unroll
            for (int w = 0; w < 8; w++) {
                S += sS[(r0 + w)*128 + col];
                Q += sQ[(r0 + w)*128 + col];
            }
            int g = tile * 2 + gsel;
            g_Gsum[g*128 + col] = S;
            g_Qprt[g*128 + col] = Q;
        }
    }
}

// ========================= classifier tail ==================================
__global__ void k_red2(const float* __restrict__ g2, const float* __restrict__ be2) {
    __shared__ float sS[256], sQ[256];
    const int f = blockIdx.x, tid = threadIdx.x;
    float s = 0.f, q = 0.f;
    for (int i = tid; i < BG; i += 256) {
        s += g_Gsum[i*F2 + f];
        q += g_Qprt[i*F2 + f];
    }
    sS[tid] = s; sQ[tid] = q; __syncthreads();
    for (int st = 128; st > 0; st >>= 1) {
        if (tid < st) { sS[tid] += sS[tid+st]; sQ[tid] += sQ[tid+st]; }
        __syncthreads();
    }
    if (tid == 0) {
        float inv = 1.f / (float)NN;
        float mu  = sS[0] * inv;
        float var = sQ[0] * inv - mu * mu;
        float a   = g2[f] * rsqrtf(var + EPSB);
        g_ab2[f]       = a;
        g_ab2[128 + f] = be2[f] - mu * a;
    }
}

__global__ void k_foldc1(const float* __restrict__ Wc1, const float* __restrict__ bc1) {
    __shared__ float sa[128], sc[128];
    const int tid = threadIdx.x;            // 256 threads
    if (tid < 128) {
        sa[tid] = g_ab2[tid] * (1.f / 64.f);
        sc[tid] = g_ab2[128 + tid];
    }
    __syncthreads();
    float bacc = bc1[tid];
    for (int c = 0; c < 128; c++) {
        float w = Wc1[c*256 + tid];
        g_Wc1f[c*256 + tid] = sa[c] * w;
        bacc += sc[c] * w;
    }
    g_bc1f[tid] = bacc;
}

__global__ __launch_bounds__(256)
void k_cls1() {
    __shared__ float gs[16 * 128];
    const int tid = threadIdx.x;
    const int blk = blockIdx.x;
    const float* G = g_Gsum + (size_t)blk * 16 * F2;
    for (int l = tid; l < 16 * 128; l += 256) gs[l] = G[l];
    __syncthreads();
    float acc[16];
    const float bb = g_bc1f[tid];
#pragma unroll
    for (int r = 0; r < 16; r++) acc[r] = bb;
    for (int c = 0; c < 128; c++) {
        float w = g_Wc1f[c*256 + tid];
#pragma unroll
        for (int r = 0; r < 16; r++) acc[r] += gs[r*128 + c] * w;
    }
    float s = 0.f, q = 0.f;
#pragma unroll
    for (int r = 0; r < 16; r++) {
        float v = fmaxf(acc[r], 0.f);
        g_C1[((size_t)blk * 16 + r) * 256 + tid] = v;
        s += v; q += v * v;
    }
    g_part3[blk*512 + tid]       = s;
    g_part3[blk*512 + 256 + tid] = q;
}

__global__ void k_red3(const float* __restrict__ gc1, const float* __restrict__ bec1,
                       const float* __restrict__ Wc2, const float* __restrict__ bc2) {
    __shared__ float red[256];
    const int tid = threadIdx.x;
    float s = 0.f, q = 0.f;
    for (int i = 0; i < 256; i++) {
        s += g_part3[i*512 + tid];
        q += g_part3[i*512 + 256 + tid];
    }
    float inv = 1.f / (float)BG;
    float mu  = s * inv;
    float var = q * inv - mu * mu;
    float a   = gc1[tid] * rsqrtf(var + EPSB);
    float c   = bec1[tid] - mu * a;
    float w   = Wc2[tid];
    g_Wc2f[tid] = a * w;
    red[tid] = c * w;
    __syncthreads();
    for (int st = 128; st > 0; st >>= 1) {
        if (tid < st) red[tid] += red[tid + st];
        __syncthreads();
    }
    if (tid == 0) g_Wc2f[256] = bc2[0] + red[0];
}

__global__ void k_z() {
    const int tid  = threadIdx.x;
    const int w    = tid >> 5;
    const int lane = tid & 31;
    const int r    = blockIdx.x * 8 + w;
    const float* row = g_C1 + (size_t)r * 256;
    float acc = 0.f;
#pragma unroll
    for (int t = 0; t < 8; t++) {
        int idx = lane + t * 32;
        acc += row[idx] * g_Wc2f[idx];
    }
    for (int off = 16; off; off >>= 1)
        acc += __shfl_down_sync(0xffffffffu, acc, off);
    if (lane == 0) g_z[r] = fmaxf(acc + g_Wc2f[256], 0.f);
}

__global__ void k_final(const float* __restrict__ gc2, const float* __restrict__ bec2,
                        float* __restrict__ out) {
    __shared__ float sS[512], sQ[512];
    const int tid = threadIdx.x;
    float s = 0.f, q = 0.f;
    float zv[8];
#pragma unroll
    for (int t = 0; t < 8; t++) {
        float v = g_z[tid + 512 * t];
        zv[t] = v; s += v; q += v * v;
    }
    sS[tid] = s; sQ[tid] = q; __syncthreads();
    for (int st = 256; st > 0; st >>= 1) {
        if (tid < st) { sS[tid] += sS[tid+st]; sQ[tid] += sQ[tid+st]; }
        __syncthreads();
    }
    float inv = 1.f / (float)BG;
    float mu  = sS[0] * inv;
    float var = sQ[0] * inv - mu * mu;
    float a   = gc2[0] * rsqrtf(var + EPSB);
    float b   = bec2[0];
#pragma unroll
    for (int t = 0; t < 8; t++) {
        float tt = a * (zv[t] - mu) + b;
        out[tid + 512 * t] = 1.f / (1.f + expf(-tt));
    }
}

extern "C" void kernel_launch(void* const* d_in, const int* in_sizes, int n_in,
                              void* d_out, int out_size) {
    const float* x    = (const float*)d_in[0];
    const float* pos  = (const float*)d_in[1];
    const float* W1   = (const float*)d_in[3];
    const float* b1   = (const float*)d_in[4];
    const float* g1   = (const float*)d_in[5];
    const float* be1  = (const float*)d_in[6];
    const float* W2   = (const float*)d_in[7];
    const float* b2   = (const float*)d_in[8];
    const float* g2   = (const float*)d_in[9];
    const float* be2  = (const float*)d_in[10];
    const float* Wc1  = (const float*)d_in[11];
    const float* bc1  = (const float*)d_in[12];
    const float* gc1  = (const float*)d_in[13];
    const float* bec1 = (const float*)d_in[14];
    const float* Wc2  = (const float*)d_in[15];
    const float* bc2  = (const float*)d_in[16];
    const float* gc2  = (const float*)d_in[17];
    const float* bec2 = (const float*)d_in[18];

    cudaFuncSetAttribute(k_ue_p,     cudaFuncAttributeMaxDynamicSharedMemorySize, UE_BYTES);
    cudaFuncSetAttribute(k_graph2_p, cudaFuncAttributeMaxDynamicSharedMemorySize, SM2_BYTES);

    k_xT      <<<2048, 256>>>(x);
    k_knn     <<<BG, 64>>>(pos);
    k_ue_p    <<<GRIDU, 512, UE_BYTES>>>(W1, b1);
    k_red1    <<<128, 256>>>(g1, be1);
    k_fold2   <<<1, 128>>>(W2, b2);
    k_graph2_p<<<GRID2, 512, SM2_BYTES>>>();
    k_red2    <<<128, 256>>>(g2, be2);
    k_foldc1  <<<1, 256>>>(Wc1, bc1);
    k_cls1    <<<256, 256>>>();
    k_red3    <<<1, 256>>>(gc1, bec1, Wc2, bc2);
    k_z       <<<512, 256>>>();
    k_final   <<<1, 512>>>(gc2, bec2, (float*)d_out);
}